// round 1
// baseline (speedup 1.0000x reference)
#include <cuda_runtime.h>
#include <math.h>

// ---------------------------------------------------------------------------
// MMDLoss: source (4096,512) f32, target (4096,512) f32 -> scalar f32
//
// total = concat(source, target)  (N=8192, D=512)
// l2[i,j] = max(sq[i]+sq[j]-2*dot(x_i,x_j), 0)
// bandwidth = sum(l2)/(N^2-N)  (closed form: 2N*sum(sq) - 2*||colsum||^2)
// kernel = sum_{i=0..4} exp(-l2/(bw*2^{i-2}+eps)) = b + b^2 + b^4 + b^8 + b^16
//   with b = exp(-l2/(4*bw+eps))
// out = Sxx/ns^2 + Syy/ns^2 - Scross/ns^2
// ---------------------------------------------------------------------------

#define NS    4096
#define NTOT  8192
#define DDIM  512
#define BM    128
#define GBLK  (NTOT / BM)              // 64
#define NBLK  (GBLK * (GBLK + 1) / 2)  // 2080

__device__ float  g_sq[NTOT];
__device__ float  g_colsum[DDIM];
__device__ float  g_c;        // log2(e) / (4*bw + eps)
__device__ double g_bins[3];  // Sxx, Syy, Scross

// ---------------- init: zero accumulators (graph replays!) -----------------
__global__ void k_init() {
    int t = threadIdx.x;
    if (t < 3) g_bins[t] = 0.0;
    if (t < DDIM) g_colsum[t] = 0.0f;
}

// ---------------- row squared norms: one warp per row ----------------------
__global__ void k_rowsq(const float* __restrict__ src, const float* __restrict__ tgt) {
    int warp = threadIdx.x >> 5;
    int lane = threadIdx.x & 31;
    int row  = blockIdx.x * 8 + warp;
    const float* p = (row < NS) ? (src + (size_t)row * DDIM)
                                : (tgt + (size_t)(row - NS) * DDIM);
    float s = 0.f;
    #pragma unroll
    for (int d = lane; d < DDIM; d += 32) {
        float v = p[d];
        s = fmaf(v, v, s);
    }
    #pragma unroll
    for (int off = 16; off > 0; off >>= 1)
        s += __shfl_xor_sync(0xffffffffu, s, off);
    if (lane == 0) g_sq[row] = s;
}

// ---------------- column sums (for sum(gram) = ||colsum||^2) ---------------
// grid (2, 32): blockIdx.x selects 256 columns, blockIdx.y selects 256 rows
__global__ void k_colsum(const float* __restrict__ src, const float* __restrict__ tgt) {
    int c  = blockIdx.x * 256 + threadIdx.x;
    int r0 = blockIdx.y * 256;
    float s = 0.f;
    for (int r = r0; r < r0 + 256; r++) {
        const float* p = (r < NS) ? (src + (size_t)r * DDIM)
                                  : (tgt + (size_t)(r - NS) * DDIM);
        s += p[c];
    }
    atomicAdd(&g_colsum[c], s);
}

// ---------------- bandwidth + exp constant ---------------------------------
__global__ void k_prep() {
    __shared__ double s1[1024];
    __shared__ double s2[1024];
    int t = threadIdx.x;
    double a = 0.0, b = 0.0;
    for (int i = t; i < NTOT; i += 1024) a += (double)g_sq[i];
    if (t < DDIM) { double v = (double)g_colsum[t]; b = v * v; }
    s1[t] = a; s2[t] = b;
    __syncthreads();
    for (int s = 512; s > 0; s >>= 1) {
        if (t < s) { s1[t] += s1[t + s]; s2[t] += s2[t + s]; }
        __syncthreads();
    }
    if (t == 0) {
        double n = (double)NTOT;
        double sum_l2 = 2.0 * n * s1[0] - 2.0 * s2[0];
        double bw = sum_l2 / (n * n - n);
        g_c = (float)(1.4426950408889634 / (4.0 * bw + 1e-8));
    }
}

// ---------------- main fused gram + kernel-sum, triangular blocks ----------
__global__ void __launch_bounds__(256) k_main(const float* __restrict__ src,
                                              const float* __restrict__ tgt) {
    __shared__ float As[16][BM];
    __shared__ float Bs[16][BM];

    int beta = blockIdx.x;
    // decode lower-tri pair (Ip >= Jp), then I = Jp <= J = Ip
    int Ip = (int)((sqrtf(8.0f * (float)beta + 1.0f) - 1.0f) * 0.5f);
    while ((Ip + 1) * (Ip + 2) / 2 <= beta) Ip++;
    while (Ip * (Ip + 1) / 2 > beta) Ip--;
    int Jp = beta - Ip * (Ip + 1) / 2;
    int I = Jp, J = Ip;                       // I <= J
    int row0 = I * BM, col0 = J * BM;

    int tid = threadIdx.x;
    int tx = tid & 15, ty = tid >> 4;
    int lrow = tid >> 2;                      // 0..63
    int lk4  = (tid & 3) * 4;                 // 0,4,8,12

    float acc[8][8];
    #pragma unroll
    for (int i = 0; i < 8; i++)
        #pragma unroll
        for (int j = 0; j < 8; j++) acc[i][j] = 0.f;

    for (int k0 = 0; k0 < DDIM; k0 += 16) {
        #pragma unroll
        for (int h = 0; h < 2; h++) {
            int r = lrow + h * 64;
            int grA = row0 + r;
            const float* pA = (grA < NS) ? (src + (size_t)grA * DDIM)
                                         : (tgt + (size_t)(grA - NS) * DDIM);
            float4 va = *(const float4*)(pA + k0 + lk4);
            As[lk4 + 0][r] = va.x; As[lk4 + 1][r] = va.y;
            As[lk4 + 2][r] = va.z; As[lk4 + 3][r] = va.w;
            int grB = col0 + r;
            const float* pB = (grB < NS) ? (src + (size_t)grB * DDIM)
                                         : (tgt + (size_t)(grB - NS) * DDIM);
            float4 vb = *(const float4*)(pB + k0 + lk4);
            Bs[lk4 + 0][r] = vb.x; Bs[lk4 + 1][r] = vb.y;
            Bs[lk4 + 2][r] = vb.z; Bs[lk4 + 3][r] = vb.w;
        }
        __syncthreads();
        #pragma unroll
        for (int kk = 0; kk < 16; kk++) {
            float a[8], b[8];
            *(float4*)(a)     = *(const float4*)&As[kk][ty * 8];
            *(float4*)(a + 4) = *(const float4*)&As[kk][ty * 8 + 4];
            *(float4*)(b)     = *(const float4*)&Bs[kk][tx * 8];
            *(float4*)(b + 4) = *(const float4*)&Bs[kk][tx * 8 + 4];
            #pragma unroll
            for (int i = 0; i < 8; i++)
                #pragma unroll
                for (int j = 0; j < 8; j++)
                    acc[i][j] = fmaf(a[i], b[j], acc[i][j]);
        }
        __syncthreads();
    }

    // epilogue: l2 -> b + b^2 + b^4 + b^8 + b^16, accumulate in double
    float c = g_c;
    float sqi[8], sqj[8];
    #pragma unroll
    for (int i = 0; i < 8; i++) sqi[i] = g_sq[row0 + ty * 8 + i];
    #pragma unroll
    for (int j = 0; j < 8; j++) sqj[j] = g_sq[col0 + tx * 8 + j];

    double accd = 0.0;
    #pragma unroll
    for (int i = 0; i < 8; i++) {
        float fs = 0.f;
        #pragma unroll
        for (int j = 0; j < 8; j++) {
            float l2 = fmaf(-2.0f, acc[i][j], sqi[i] + sqj[j]);
            l2 = fmaxf(l2, 0.0f);
            float b1 = exp2f(-l2 * c);
            float p2 = b1 * b1;
            float p4 = p2 * p2;
            float p8 = p4 * p4;
            float p16 = p8 * p8;
            fs += b1 + p2 + p4 + p8 + p16;
        }
        accd += (double)fs;
    }

    __shared__ double sred[256];
    sred[tid] = accd;
    __syncthreads();
    for (int s = 128; s > 0; s >>= 1) {
        if (tid < s) sred[tid] += sred[tid + s];
        __syncthreads();
    }
    if (tid == 0) {
        double v = sred[0] * ((I == J) ? 1.0 : 2.0);
        int bin = (J < GBLK / 2) ? 0 : ((I >= GBLK / 2) ? 1 : 2);
        atomicAdd(&g_bins[bin], v);
    }
}

// ---------------- finalize -------------------------------------------------
__global__ void k_final(float* out) {
    double ns2 = (double)NS * (double)NS;
    out[0] = (float)((g_bins[0] + g_bins[1] - g_bins[2]) / ns2);
}

extern "C" void kernel_launch(void* const* d_in, const int* in_sizes, int n_in,
                              void* d_out, int out_size) {
    const float* src = (const float*)d_in[0];
    const float* tgt = (const float*)d_in[1];
    float* out = (float*)d_out;

    k_init<<<1, 512>>>();
    k_rowsq<<<NTOT / 8, 256>>>(src, tgt);
    k_colsum<<<dim3(2, 32), 256>>>(src, tgt);
    k_prep<<<1, 1024>>>();
    k_main<<<NBLK, 256>>>(src, tgt);
    k_final<<<1, 1>>>(out);
}

// round 3
// speedup vs baseline: 2.5884x; 2.5884x over previous
#include <cuda_runtime.h>
#include <cuda_bf16.h>
#include <math.h>
#include <stdint.h>

// ---------------------------------------------------------------------------
// MMDLoss: source (4096,512) f32, target (4096,512) f32 -> scalar f32
//
// Gram via 3xBF16 split (hi*hi + hi*lo + lo*hi) on mma.sync.m16n8k16 (HMMA,
// baseline PTX -- tcgen05 is 'a'-target gated and the harness targets sm_103).
// Triangular 128x128 tiles. Bandwidth closed-form:
//   sum(l2) = 2N*sum(sq) - 2*||colsum||^2
// 5-bandwidth RBF collapses to b + b^2 + b^4 + b^8 + b^16, b = exp(-l2/(4bw)).
// ---------------------------------------------------------------------------

#define NS    4096
#define NTOT  8192
#define DDIM  512
#define BM    128
#define GBLK  64
#define NBLK  2080            // 64*65/2 triangular tile pairs
#define KC    64              // K elements per chunk
#define NCH   8               // 512/64

#define TILEB 16384           // 128 rows * 128 bytes (64 bf16)
#define BUFB  (4 * TILEB)     // Ahi, Alo, Bhi, Blo
#define SM_BUF 1024
#define SMEM_DYN (SM_BUF + 2 * BUFB)   // 132096 bytes

__device__ __nv_bfloat16 g_hi[NTOT * DDIM];   // 8 MB
__device__ __nv_bfloat16 g_lo[NTOT * DDIM];   // 8 MB
__device__ float  g_sq[NTOT];
__device__ float  g_colsum[DDIM];
__device__ float  g_c;        // log2(e) / (4*bw + eps)
__device__ double g_bins[3];  // Sxx, Syy, Scross

// ------------------------------ PTX helpers -------------------------------
__device__ __forceinline__ uint32_t smem_u32(const void* p) {
    uint32_t a;
    asm("{ .reg .u64 t; cvta.to.shared.u64 t, %1; cvt.u32.u64 %0, t; }"
        : "=r"(a) : "l"(p));
    return a;
}
__device__ __forceinline__ void cp_async16(uint32_t sa, const void* g) {
    asm volatile("cp.async.cg.shared.global [%0], [%1], 16;"
                 :: "r"(sa), "l"(g) : "memory");
}
#define CP_COMMIT() asm volatile("cp.async.commit_group;" ::: "memory")
#define CP_WAIT1()  asm volatile("cp.async.wait_group 1;" ::: "memory")
#define CP_WAIT0()  asm volatile("cp.async.wait_group 0;" ::: "memory")

__device__ __forceinline__ void ldsm_x4(uint32_t& r0, uint32_t& r1,
                                        uint32_t& r2, uint32_t& r3, uint32_t a) {
    asm volatile("ldmatrix.sync.aligned.m8n8.x4.shared.b16 {%0,%1,%2,%3}, [%4];"
                 : "=r"(r0), "=r"(r1), "=r"(r2), "=r"(r3) : "r"(a));
}
__device__ __forceinline__ void mma16816(float* c, const uint32_t* a,
                                         uint32_t b0, uint32_t b1) {
    asm volatile(
        "mma.sync.aligned.m16n8k16.row.col.f32.bf16.bf16.f32 "
        "{%0,%1,%2,%3}, {%4,%5,%6,%7}, {%8,%9}, {%0,%1,%2,%3};"
        : "+f"(c[0]), "+f"(c[1]), "+f"(c[2]), "+f"(c[3])
        : "r"(a[0]), "r"(a[1]), "r"(a[2]), "r"(a[3]), "r"(b0), "r"(b1));
}
__device__ __forceinline__ uint32_t swz(uint32_t bo) {
    return bo ^ ((bo >> 3) & 0x70);
}

// ---------------- init: zero accumulators (graph replays!) -----------------
__global__ void k_init() {
    int t = threadIdx.x;
    if (t < 3) g_bins[t] = 0.0;
    if (t < DDIM) g_colsum[t] = 0.0f;
}

// --------- convert f32 -> bf16 hi/lo + row squared norms (one warp/row) ----
__global__ void k_convert(const float* __restrict__ src, const float* __restrict__ tgt) {
    int warp = threadIdx.x >> 5;
    int lane = threadIdx.x & 31;
    int row  = blockIdx.x * 8 + warp;
    const float* p = (row < NS) ? (src + (size_t)row * DDIM)
                                : (tgt + (size_t)(row - NS) * DDIM);
    size_t gb = (size_t)row * DDIM;
    float s = 0.f;
    #pragma unroll
    for (int v = 0; v < 4; v++) {
        int e = (lane + v * 32) * 4;
        float4 f = *(const float4*)(p + e);
        s = fmaf(f.x, f.x, s); s = fmaf(f.y, f.y, s);
        s = fmaf(f.z, f.z, s); s = fmaf(f.w, f.w, s);
        union { __nv_bfloat16 h[4]; uint2 u; } H, L;
        H.h[0] = __float2bfloat16(f.x); L.h[0] = __float2bfloat16(f.x - __bfloat162float(H.h[0]));
        H.h[1] = __float2bfloat16(f.y); L.h[1] = __float2bfloat16(f.y - __bfloat162float(H.h[1]));
        H.h[2] = __float2bfloat16(f.z); L.h[2] = __float2bfloat16(f.z - __bfloat162float(H.h[2]));
        H.h[3] = __float2bfloat16(f.w); L.h[3] = __float2bfloat16(f.w - __bfloat162float(H.h[3]));
        *(uint2*)(g_hi + gb + e) = H.u;
        *(uint2*)(g_lo + gb + e) = L.u;
    }
    #pragma unroll
    for (int off = 16; off > 0; off >>= 1)
        s += __shfl_xor_sync(0xffffffffu, s, off);
    if (lane == 0) g_sq[row] = s;
}

// ---------------- column sums (for sum(gram) = ||colsum||^2) ---------------
__global__ void k_colsum(const float* __restrict__ src, const float* __restrict__ tgt) {
    int c  = blockIdx.x * 256 + threadIdx.x;
    int r0 = blockIdx.y * 256;
    float s = 0.f;
    for (int r = r0; r < r0 + 256; r++) {
        const float* p = (r < NS) ? (src + (size_t)r * DDIM)
                                  : (tgt + (size_t)(r - NS) * DDIM);
        s += p[c];
    }
    atomicAdd(&g_colsum[c], s);
}

// ---------------- bandwidth + exp constant ---------------------------------
__global__ void k_prep() {
    __shared__ double s1[1024];
    __shared__ double s2[1024];
    int t = threadIdx.x;
    double a = 0.0, b = 0.0;
    for (int i = t; i < NTOT; i += 1024) a += (double)g_sq[i];
    if (t < DDIM) { double v = (double)g_colsum[t]; b = v * v; }
    s1[t] = a; s2[t] = b;
    __syncthreads();
    for (int s = 512; s > 0; s >>= 1) {
        if (t < s) { s1[t] += s1[t + s]; s2[t] += s2[t + s]; }
        __syncthreads();
    }
    if (t == 0) {
        double n = (double)NTOT;
        double sum_l2 = 2.0 * n * s1[0] - 2.0 * s2[0];
        double bw = sum_l2 / (n * n - n);
        g_c = (float)(1.4426950408889634 / (4.0 * bw + 1e-8));
    }
}

// ---------------- main: HMMA gram + fused RBF epilogue ---------------------
__global__ void __launch_bounds__(256, 1) k_main() {
    extern __shared__ char smem[];
    float* s_sqi = (float*)smem;          // [128]
    float* s_sqj = (float*)(smem + 512);  // [128]
    uint32_t sb = smem_u32(smem);
    int tid = threadIdx.x;
    int wid = tid >> 5;
    int lid = tid & 31;
    int wm = wid & 3, wn = wid >> 2;      // warp grid 4 x 2 (m x n)

    // triangular tile decode: I <= J
    int beta = blockIdx.x;
    int Ip = (int)((sqrtf(8.0f * (float)beta + 1.0f) - 1.0f) * 0.5f);
    while ((Ip + 1) * (Ip + 2) / 2 <= beta) Ip++;
    while (Ip * (Ip + 1) / 2 > beta) Ip--;
    int Jp = beta - Ip * (Ip + 1) / 2;
    int I = Jp, J = Ip;
    int row0 = I * BM, col0 = J * BM;

    if (tid < BM)       s_sqi[tid] = g_sq[row0 + tid];
    else                s_sqj[tid - BM] = g_sq[col0 + tid - BM];

    // --- async chunk loader: chunk c -> buffer (c&1): Ahi, Alo, Bhi, Blo ---
    auto load_chunk = [&](int c) {
        uint32_t base = sb + SM_BUF + (c & 1) * BUFB;
        int k0 = c * KC;
        #pragma unroll
        for (int p = 0; p < 4; p++) {
            int q = tid + 256 * p;            // 1024 segments of 16B per array
            int r = q >> 3, sg = q & 7;
            uint32_t sw = swz(r * 128 + sg * 16);
            size_t eoA = (size_t)(row0 + r) * DDIM + k0 + sg * 8;
            size_t eoB = (size_t)(col0 + r) * DDIM + k0 + sg * 8;
            cp_async16(base + 0 * TILEB + sw, g_hi + eoA);
            cp_async16(base + 1 * TILEB + sw, g_lo + eoA);
            cp_async16(base + 2 * TILEB + sw, g_hi + eoB);
            cp_async16(base + 3 * TILEB + sw, g_lo + eoB);
        }
        CP_COMMIT();
    };

    float acc[2][8][4];
    #pragma unroll
    for (int mt = 0; mt < 2; mt++)
        #pragma unroll
        for (int nt = 0; nt < 8; nt++)
            #pragma unroll
            for (int k = 0; k < 4; k++) acc[mt][nt][k] = 0.f;

    load_chunk(0);
    load_chunk(1);

    // per-lane fragment addresses (row/col within 128x64 tile)
    int fr = lid & 15;                 // row within 16-row group
    uint32_t fcol = ((lid >> 4) & 1) * 16;  // 0 or 16 bytes (k-half)

    for (int c = 0; c < NCH; c++) {
        if (c < NCH - 1) CP_WAIT1(); else CP_WAIT0();
        __syncthreads();

        uint32_t base = sb + SM_BUF + (c & 1) * BUFB;
        #pragma unroll
        for (int kk = 0; kk < 4; kk++) {
            uint32_t kb = kk * 32 + fcol;
            uint32_t ah[2][4], al[2][4];
            #pragma unroll
            for (int mt = 0; mt < 2; mt++) {
                uint32_t ro = (wm * 32 + mt * 16 + fr) * 128 + kb;
                uint32_t sw = swz(ro);
                ldsm_x4(ah[mt][0], ah[mt][1], ah[mt][2], ah[mt][3], base + sw);
                ldsm_x4(al[mt][0], al[mt][1], al[mt][2], al[mt][3], base + TILEB + sw);
            }
            #pragma unroll
            for (int p = 0; p < 4; p++) {
                uint32_t ro = (wn * 64 + p * 16 + fr) * 128 + kb;
                uint32_t sw = swz(ro);
                uint32_t bh0, bh1, bh2, bh3, bl0, bl1, bl2, bl3;
                ldsm_x4(bh0, bh1, bh2, bh3, base + 2 * TILEB + sw);
                ldsm_x4(bl0, bl1, bl2, bl3, base + 3 * TILEB + sw);
                #pragma unroll
                for (int mt = 0; mt < 2; mt++) {
                    mma16816(acc[mt][2 * p],     ah[mt], bh0, bh2);
                    mma16816(acc[mt][2 * p],     ah[mt], bl0, bl2);
                    mma16816(acc[mt][2 * p],     al[mt], bh0, bh2);
                    mma16816(acc[mt][2 * p + 1], ah[mt], bh1, bh3);
                    mma16816(acc[mt][2 * p + 1], ah[mt], bl1, bl3);
                    mma16816(acc[mt][2 * p + 1], al[mt], bh1, bh3);
                }
            }
        }
        __syncthreads();
        if (c + 2 < NCH) load_chunk(c + 2);
    }

    // ---- epilogue: registers -> l2 -> b + b^2 + b^4 + b^8 + b^16 ----------
    float cst = g_c;
    int g = lid >> 2, t4 = lid & 3;
    double accd = 0.0;
    #pragma unroll
    for (int mt = 0; mt < 2; mt++) {
        float sqi0 = s_sqi[wm * 32 + mt * 16 + g];
        float sqi1 = s_sqi[wm * 32 + mt * 16 + g + 8];
        float fs = 0.f;
        #pragma unroll
        for (int nt = 0; nt < 8; nt++) {
            float sqj0 = s_sqj[wn * 64 + nt * 8 + 2 * t4];
            float sqj1 = s_sqj[wn * 64 + nt * 8 + 2 * t4 + 1];
            #pragma unroll
            for (int k = 0; k < 4; k++) {
                float si = (k < 2) ? sqi0 : sqi1;
                float sj = (k & 1) ? sqj1 : sqj0;
                float l2 = fmaxf(fmaf(-2.0f, acc[mt][nt][k], si + sj), 0.0f);
                float b1 = exp2f(-l2 * cst);
                float p2 = b1 * b1;
                float p4 = p2 * p2;
                float p8 = p4 * p4;
                float p16 = p8 * p8;
                fs += b1 + p2 + p4 + p8 + p16;
            }
        }
        accd += (double)fs;
    }

    __shared__ double sred[256];
    sred[tid] = accd;
    __syncthreads();
    for (int s = 128; s > 0; s >>= 1) {
        if (tid < s) sred[tid] += sred[tid + s];
        __syncthreads();
    }
    if (tid == 0) {
        double v = sred[0] * ((I == J) ? 1.0 : 2.0);
        int bin = (J < GBLK / 2) ? 0 : ((I >= GBLK / 2) ? 1 : 2);
        atomicAdd(&g_bins[bin], v);
    }
}

// ---------------- finalize -------------------------------------------------
__global__ void k_final(float* out) {
    double ns2 = (double)NS * (double)NS;
    out[0] = (float)((g_bins[0] + g_bins[1] - g_bins[2]) / ns2);
}

extern "C" void kernel_launch(void* const* d_in, const int* in_sizes, int n_in,
                              void* d_out, int out_size) {
    const float* src = (const float*)d_in[0];
    const float* tgt = (const float*)d_in[1];
    float* out = (float*)d_out;

    cudaFuncSetAttribute(k_main, cudaFuncAttributeMaxDynamicSharedMemorySize,
                         SMEM_DYN);
    k_init<<<1, 512>>>();
    k_convert<<<NTOT / 8, 256>>>(src, tgt);
    k_colsum<<<dim3(2, 32), 256>>>(src, tgt);
    k_prep<<<1, 1024>>>();
    k_main<<<NBLK, 256, SMEM_DYN>>>();
    k_final<<<1, 1>>>(out);
}

// round 4
// speedup vs baseline: 2.8068x; 1.0844x over previous
#include <cuda_runtime.h>
#include <cuda_bf16.h>
#include <math.h>
#include <stdint.h>

// ---------------------------------------------------------------------------
// MMDLoss: source (4096,512) f32, target (4096,512) f32 -> scalar f32
//
// Gram via 3xBF16 split (hi*hi + hi*lo + lo*hi) on mma.sync.m16n8k16 (HMMA).
// Triangular 128x128 tiles, KC=32 chunks (SW64), 2 CTAs/SM.
// Bandwidth closed-form: sum(l2) = 2N*sum(sq) - 2*||colsum||^2.
// 5-bandwidth RBF collapses to b + b^2 + b^4 + b^8 + b^16, b = exp(-l2/(4bw)).
// ---------------------------------------------------------------------------

#define NS    4096
#define NTOT  8192
#define DDIM  512
#define BM    128
#define GBLK  64
#define NBLK  2080            // 64*65/2 triangular tile pairs
#define KC    32              // K elements per chunk (32 bf16 = 64B row)
#define NCH   16              // 512/32

#define TILEB 8192            // 128 rows * 64 bytes
#define BUFB  (4 * TILEB)     // Ahi, Alo, Bhi, Blo = 32KB
#define SM_BUF 1024
#define SMEM_DYN (SM_BUF + 2 * BUFB)   // 66560 bytes -> 2 CTAs/SM

__device__ __nv_bfloat16 g_hi[NTOT * DDIM];   // 8 MB
__device__ __nv_bfloat16 g_lo[NTOT * DDIM];   // 8 MB
__device__ float  g_sq[NTOT];
__device__ float  g_colsum[DDIM];
__device__ float  g_c;        // log2(e) / (4*bw + eps)
__device__ double g_bins[3];  // Sxx, Syy, Scross

// ------------------------------ PTX helpers -------------------------------
__device__ __forceinline__ uint32_t smem_u32(const void* p) {
    uint32_t a;
    asm("{ .reg .u64 t; cvta.to.shared.u64 t, %1; cvt.u32.u64 %0, t; }"
        : "=r"(a) : "l"(p));
    return a;
}
__device__ __forceinline__ void cp_async16(uint32_t sa, const void* g) {
    asm volatile("cp.async.cg.shared.global [%0], [%1], 16;"
                 :: "r"(sa), "l"(g) : "memory");
}
#define CP_COMMIT() asm volatile("cp.async.commit_group;" ::: "memory")
#define CP_WAIT1()  asm volatile("cp.async.wait_group 1;" ::: "memory")
#define CP_WAIT0()  asm volatile("cp.async.wait_group 0;" ::: "memory")

__device__ __forceinline__ void ldsm_x4(uint32_t& r0, uint32_t& r1,
                                        uint32_t& r2, uint32_t& r3, uint32_t a) {
    asm volatile("ldmatrix.sync.aligned.m8n8.x4.shared.b16 {%0,%1,%2,%3}, [%4];"
                 : "=r"(r0), "=r"(r1), "=r"(r2), "=r"(r3) : "r"(a));
}
__device__ __forceinline__ void mma16816(float* c, const uint32_t* a,
                                         uint32_t b0, uint32_t b1) {
    asm volatile(
        "mma.sync.aligned.m16n8k16.row.col.f32.bf16.bf16.f32 "
        "{%0,%1,%2,%3}, {%4,%5,%6,%7}, {%8,%9}, {%0,%1,%2,%3};"
        : "+f"(c[0]), "+f"(c[1]), "+f"(c[2]), "+f"(c[3])
        : "r"(a[0]), "r"(a[1]), "r"(a[2]), "r"(a[3]), "r"(b0), "r"(b1));
}
__device__ __forceinline__ float ex2_approx(float x) {
    float r;
    asm("ex2.approx.ftz.f32 %0, %1;" : "=f"(r) : "f"(x));
    return r;
}
// SW64 swizzle for 64-byte rows (atom: 8 rows x 64B)
__device__ __forceinline__ uint32_t swz64(uint32_t bo) {
    return bo ^ ((bo >> 3) & 0x30);
}

// --------- convert f32 -> bf16 hi/lo + row sq norms; block 0 also zeroes ---
__global__ void k_convert(const float* __restrict__ src, const float* __restrict__ tgt) {
    if (blockIdx.x == 0) {
        int t = threadIdx.x;
        if (t < 3) g_bins[t] = 0.0;
        g_colsum[t] = 0.0f;
        g_colsum[t + 256] = 0.0f;
    }
    int warp = threadIdx.x >> 5;
    int lane = threadIdx.x & 31;
    int row  = blockIdx.x * 8 + warp;
    const float* p = (row < NS) ? (src + (size_t)row * DDIM)
                                : (tgt + (size_t)(row - NS) * DDIM);
    size_t gb = (size_t)row * DDIM;
    float s = 0.f;
    #pragma unroll
    for (int v = 0; v < 4; v++) {
        int e = (lane + v * 32) * 4;
        float4 f = *(const float4*)(p + e);
        s = fmaf(f.x, f.x, s); s = fmaf(f.y, f.y, s);
        s = fmaf(f.z, f.z, s); s = fmaf(f.w, f.w, s);
        union { __nv_bfloat16 h[4]; uint2 u; } H, L;
        H.h[0] = __float2bfloat16(f.x); L.h[0] = __float2bfloat16(f.x - __bfloat162float(H.h[0]));
        H.h[1] = __float2bfloat16(f.y); L.h[1] = __float2bfloat16(f.y - __bfloat162float(H.h[1]));
        H.h[2] = __float2bfloat16(f.z); L.h[2] = __float2bfloat16(f.z - __bfloat162float(H.h[2]));
        H.h[3] = __float2bfloat16(f.w); L.h[3] = __float2bfloat16(f.w - __bfloat162float(H.h[3]));
        *(uint2*)(g_hi + gb + e) = H.u;
        *(uint2*)(g_lo + gb + e) = L.u;
    }
    #pragma unroll
    for (int off = 16; off > 0; off >>= 1)
        s += __shfl_xor_sync(0xffffffffu, s, off);
    if (lane == 0) g_sq[row] = s;
}

// ---------------- column sums (for sum(gram) = ||colsum||^2) ---------------
__global__ void k_colsum(const float* __restrict__ src, const float* __restrict__ tgt) {
    int c  = blockIdx.x * 256 + threadIdx.x;
    int r0 = blockIdx.y * 256;
    float s = 0.f;
    for (int r = r0; r < r0 + 256; r++) {
        const float* p = (r < NS) ? (src + (size_t)r * DDIM)
                                  : (tgt + (size_t)(r - NS) * DDIM);
        s += p[c];
    }
    atomicAdd(&g_colsum[c], s);
}

// ---------------- bandwidth + exp constant (256 threads) -------------------
__global__ void k_prep() {
    __shared__ double sh1[8], sh2[8];
    int t = threadIdx.x;
    int warp = t >> 5, lane = t & 31;
    double a = 0.0, b = 0.0;
    const float4* sq4 = (const float4*)g_sq;
    #pragma unroll
    for (int i = 0; i < 8; i++) {
        float4 f = sq4[t + 256 * i];
        a += (double)f.x + (double)f.y + (double)f.z + (double)f.w;
    }
    #pragma unroll
    for (int i = 0; i < 2; i++) {
        double v = (double)g_colsum[t + 256 * i];
        b += v * v;
    }
    #pragma unroll
    for (int off = 16; off > 0; off >>= 1) {
        a += __shfl_xor_sync(0xffffffffu, a, off);
        b += __shfl_xor_sync(0xffffffffu, b, off);
    }
    if (lane == 0) { sh1[warp] = a; sh2[warp] = b; }
    __syncthreads();
    if (t == 0) {
        double A = 0.0, B = 0.0;
        #pragma unroll
        for (int w = 0; w < 8; w++) { A += sh1[w]; B += sh2[w]; }
        double n = (double)NTOT;
        double sum_l2 = 2.0 * n * A - 2.0 * B;
        double bw = sum_l2 / (n * n - n);
        g_c = (float)(1.4426950408889634 / (4.0 * bw + 1e-8));
    }
}

// ---------------- main: HMMA gram + fused RBF epilogue ---------------------
__global__ void __launch_bounds__(256, 2) k_main() {
    extern __shared__ char smem[];
    float* s_sqi = (float*)smem;          // [128] = g_sq * cst
    float* s_sqj = (float*)(smem + 512);  // [128] = g_sq * cst
    uint32_t sb = smem_u32(smem);
    int tid = threadIdx.x;
    int wid = tid >> 5;
    int lid = tid & 31;
    int wm = wid & 3, wn = wid >> 2;      // warp grid 4 x 2 (m x n)

    // triangular tile decode: I <= J
    int beta = blockIdx.x;
    int Ip = (int)((sqrtf(8.0f * (float)beta + 1.0f) - 1.0f) * 0.5f);
    while ((Ip + 1) * (Ip + 2) / 2 <= beta) Ip++;
    while (Ip * (Ip + 1) / 2 > beta) Ip--;
    int Jp = beta - Ip * (Ip + 1) / 2;
    int I = Jp, J = Ip;
    int row0 = I * BM, col0 = J * BM;

    float cst = g_c;
    if (tid < BM)       s_sqi[tid] = g_sq[row0 + tid] * cst;
    else                s_sqj[tid - BM] = g_sq[col0 + tid - BM] * cst;

    // --- async chunk loader: chunk c -> buffer (c&1): Ahi, Alo, Bhi, Blo ---
    // each array 128 rows x 64B, SW64 swizzle; 2048 16B-segments total
    auto load_chunk = [&](int c) {
        uint32_t base = sb + SM_BUF + (c & 1) * BUFB;
        int k0 = c * KC;
        #pragma unroll
        for (int p = 0; p < 8; p++) {
            int q = tid + 256 * p;            // 0..2047
            int arr = q >> 9;                 // 0..3
            int s = q & 511;
            int r = s >> 2, c4 = s & 3;
            uint32_t sw = swz64(r * 64 + c4 * 16);
            const __nv_bfloat16* gsrc;
            size_t eo;
            if (arr < 2) eo = (size_t)(row0 + r) * DDIM + k0 + c4 * 8;
            else         eo = (size_t)(col0 + r) * DDIM + k0 + c4 * 8;
            gsrc = ((arr & 1) == 0) ? g_hi : g_lo;
            cp_async16(base + arr * TILEB + sw, gsrc + eo);
        }
        CP_COMMIT();
    };

    float acc[2][8][4];
    #pragma unroll
    for (int mt = 0; mt < 2; mt++)
        #pragma unroll
        for (int nt = 0; nt < 8; nt++)
            #pragma unroll
            for (int k = 0; k < 4; k++) acc[mt][nt][k] = 0.f;

    load_chunk(0);
    load_chunk(1);

    int fr = lid & 15;                       // row within 16-row group
    uint32_t fcol = ((lid >> 4) & 1) * 16;   // 16B k-half

    for (int c = 0; c < NCH; c++) {
        if (c < NCH - 1) CP_WAIT1(); else CP_WAIT0();
        __syncthreads();

        uint32_t base = sb + SM_BUF + (c & 1) * BUFB;
        #pragma unroll
        for (int kk = 0; kk < 2; kk++) {
            uint32_t kb = kk * 32 + fcol;
            uint32_t ah[2][4], al[2][4];
            #pragma unroll
            for (int mt = 0; mt < 2; mt++) {
                uint32_t sw = swz64((wm * 32 + mt * 16 + fr) * 64 + kb);
                ldsm_x4(ah[mt][0], ah[mt][1], ah[mt][2], ah[mt][3], base + sw);
                ldsm_x4(al[mt][0], al[mt][1], al[mt][2], al[mt][3], base + TILEB + sw);
            }
            #pragma unroll
            for (int p = 0; p < 4; p++) {
                uint32_t sw = swz64((wn * 64 + p * 16 + fr) * 64 + kb);
                uint32_t bh0, bh1, bh2, bh3, bl0, bl1, bl2, bl3;
                ldsm_x4(bh0, bh1, bh2, bh3, base + 2 * TILEB + sw);
                ldsm_x4(bl0, bl1, bl2, bl3, base + 3 * TILEB + sw);
                #pragma unroll
                for (int mt = 0; mt < 2; mt++) {
                    mma16816(acc[mt][2 * p],     ah[mt], bh0, bh2);
                    mma16816(acc[mt][2 * p],     ah[mt], bl0, bl2);
                    mma16816(acc[mt][2 * p],     al[mt], bh0, bh2);
                    mma16816(acc[mt][2 * p + 1], ah[mt], bh1, bh3);
                    mma16816(acc[mt][2 * p + 1], ah[mt], bl1, bl3);
                    mma16816(acc[mt][2 * p + 1], al[mt], bh1, bh3);
                }
            }
        }
        __syncthreads();
        if (c + 2 < NCH) load_chunk(c + 2);
    }

    // ---- epilogue: acc -> t = min(2c*dot - (sqi+sqj)*c, 0); b=2^t;
    //               fs += b + b^2 + b^4 + b^8 + b^16
    float c2 = 2.0f * cst;
    int g = lid >> 2, t4 = lid & 3;
    double accd = 0.0;
    #pragma unroll
    for (int mt = 0; mt < 2; mt++) {
        float si0 = s_sqi[wm * 32 + mt * 16 + g];
        float si1 = s_sqi[wm * 32 + mt * 16 + g + 8];
        float fs = 0.f;
        #pragma unroll
        for (int nt = 0; nt < 8; nt++) {
            float sj0 = s_sqj[wn * 64 + nt * 8 + 2 * t4];
            float sj1 = s_sqj[wn * 64 + nt * 8 + 2 * t4 + 1];
            #pragma unroll
            for (int k = 0; k < 4; k++) {
                float si = (k < 2) ? si0 : si1;
                float sj = (k & 1) ? sj1 : sj0;
                float t = fminf(fmaf(c2, acc[mt][nt][k], -(si + sj)), 0.0f);
                float b1 = ex2_approx(t);
                float p2 = b1 * b1;
                float p4 = p2 * p2;
                float p8 = p4 * p4;
                float p16 = p8 * p8;
                fs += (b1 + p2) + (p4 + p8) + p16;
            }
        }
        accd += (double)fs;
    }

    __shared__ double sred[256];
    sred[tid] = accd;
    __syncthreads();
    for (int s = 128; s > 0; s >>= 1) {
        if (tid < s) sred[tid] += sred[tid + s];
        __syncthreads();
    }
    if (tid == 0) {
        double v = sred[0] * ((I == J) ? 1.0 : 2.0);
        int bin = (J < GBLK / 2) ? 0 : ((I >= GBLK / 2) ? 1 : 2);
        atomicAdd(&g_bins[bin], v);
    }
}

// ---------------- finalize -------------------------------------------------
__global__ void k_final(float* out) {
    double ns2 = (double)NS * (double)NS;
    out[0] = (float)((g_bins[0] + g_bins[1] - g_bins[2]) / ns2);
}

extern "C" void kernel_launch(void* const* d_in, const int* in_sizes, int n_in,
                              void* d_out, int out_size) {
    const float* src = (const float*)d_in[0];
    const float* tgt = (const float*)d_in[1];
    float* out = (float*)d_out;

    cudaFuncSetAttribute(k_main, cudaFuncAttributeMaxDynamicSharedMemorySize,
                         SMEM_DYN);
    k_convert<<<NTOT / 8, 256>>>(src, tgt);
    k_colsum<<<dim3(2, 32), 256>>>(src, tgt);
    k_prep<<<1, 256>>>();
    k_main<<<NBLK, 256, SMEM_DYN>>>();
    k_final<<<1, 1>>>(out);
}

// round 5
// speedup vs baseline: 2.8626x; 1.0199x over previous
#include <cuda_runtime.h>
#include <cuda_bf16.h>
#include <math.h>
#include <stdint.h>

// ---------------------------------------------------------------------------
// MMDLoss: source (4096,512) f32, target (4096,512) f32 -> scalar f32
//
// Gram via 3xBF16 split (hi*hi + hi*lo + lo*hi) on mma.sync.m16n8k16 (HMMA).
// Triangular 128x128 tiles, KC=32 chunks (SW64), 3-stage cp.async pipeline,
// 2 CTAs/SM. Bandwidth closed-form: sum(l2) = 2N*sum(sq) - 2*||colsum||^2.
// 5-bandwidth RBF collapses to b + b^2 + b^4 + b^8 + b^16, b = exp(-l2/(4bw)).
// ---------------------------------------------------------------------------

#define NS    4096
#define NTOT  8192
#define DDIM  512
#define BM    128
#define GBLK  64
#define NBLK  2080            // 64*65/2 triangular tile pairs
#define KC    32              // K elements per chunk (32 bf16 = 64B row)
#define NCH   16              // 512/32

#define TILEB 8192            // 128 rows * 64 bytes
#define BUFB  (4 * TILEB)     // Ahi, Alo, Bhi, Blo = 32KB
#define SM_BUF 1024
#define SMEM_DYN (SM_BUF + 3 * BUFB)   // 99328 bytes -> 2 CTAs/SM (regs bind)

__device__ __nv_bfloat16 g_hi[NTOT * DDIM];   // 8 MB
__device__ __nv_bfloat16 g_lo[NTOT * DDIM];   // 8 MB
__device__ float  g_sq[NTOT];
__device__ float  g_colsum[DDIM];   // zero-init at load; k_final re-zeroes
__device__ float  g_c;              // log2(e) / (4*bw + eps)
__device__ double g_bins[3];        // Sxx, Syy, Scross; k_final re-zeroes

// ------------------------------ PTX helpers -------------------------------
__device__ __forceinline__ uint32_t smem_u32(const void* p) {
    uint32_t a;
    asm("{ .reg .u64 t; cvta.to.shared.u64 t, %1; cvt.u32.u64 %0, t; }"
        : "=r"(a) : "l"(p));
    return a;
}
__device__ __forceinline__ void cp_async16(uint32_t sa, const void* g) {
    asm volatile("cp.async.cg.shared.global [%0], [%1], 16;"
                 :: "r"(sa), "l"(g) : "memory");
}
#define CP_COMMIT() asm volatile("cp.async.commit_group;" ::: "memory")
#define CP_WAIT1()  asm volatile("cp.async.wait_group 1;" ::: "memory")
#define CP_WAIT0()  asm volatile("cp.async.wait_group 0;" ::: "memory")

__device__ __forceinline__ void ldsm_x4(uint32_t& r0, uint32_t& r1,
                                        uint32_t& r2, uint32_t& r3, uint32_t a) {
    asm volatile("ldmatrix.sync.aligned.m8n8.x4.shared.b16 {%0,%1,%2,%3}, [%4];"
                 : "=r"(r0), "=r"(r1), "=r"(r2), "=r"(r3) : "r"(a));
}
__device__ __forceinline__ void mma16816(float* c, const uint32_t* a,
                                         uint32_t b0, uint32_t b1) {
    asm volatile(
        "mma.sync.aligned.m16n8k16.row.col.f32.bf16.bf16.f32 "
        "{%0,%1,%2,%3}, {%4,%5,%6,%7}, {%8,%9}, {%0,%1,%2,%3};"
        : "+f"(c[0]), "+f"(c[1]), "+f"(c[2]), "+f"(c[3])
        : "r"(a[0]), "r"(a[1]), "r"(a[2]), "r"(a[3]), "r"(b0), "r"(b1));
}
__device__ __forceinline__ float ex2_approx(float x) {
    float r;
    asm("ex2.approx.ftz.f32 %0, %1;" : "=f"(r) : "f"(x));
    return r;
}
// SW64 swizzle for 64-byte rows (atom: 8 rows x 64B)
__device__ __forceinline__ uint32_t swz64(uint32_t bo) {
    return bo ^ ((bo >> 3) & 0x30);
}

// --- convert f32 -> bf16 hi/lo + row sq norms + fused column sums ----------
__global__ void k_convert(const float* __restrict__ src, const float* __restrict__ tgt) {
    __shared__ float s_col[DDIM];
    int t = threadIdx.x;
    s_col[t] = 0.f; s_col[t + 256] = 0.f;
    __syncthreads();

    int warp = t >> 5;
    int lane = t & 31;
    int row  = blockIdx.x * 8 + warp;
    const float* p = (row < NS) ? (src + (size_t)row * DDIM)
                                : (tgt + (size_t)(row - NS) * DDIM);
    size_t gb = (size_t)row * DDIM;
    float s = 0.f;
    #pragma unroll
    for (int v = 0; v < 4; v++) {
        int e = (lane + v * 32) * 4;
        float4 f = *(const float4*)(p + e);
        s = fmaf(f.x, f.x, s); s = fmaf(f.y, f.y, s);
        s = fmaf(f.z, f.z, s); s = fmaf(f.w, f.w, s);
        atomicAdd(&s_col[e + 0], f.x);
        atomicAdd(&s_col[e + 1], f.y);
        atomicAdd(&s_col[e + 2], f.z);
        atomicAdd(&s_col[e + 3], f.w);
        union { __nv_bfloat16 h[4]; uint2 u; } H, L;
        H.h[0] = __float2bfloat16(f.x); L.h[0] = __float2bfloat16(f.x - __bfloat162float(H.h[0]));
        H.h[1] = __float2bfloat16(f.y); L.h[1] = __float2bfloat16(f.y - __bfloat162float(H.h[1]));
        H.h[2] = __float2bfloat16(f.z); L.h[2] = __float2bfloat16(f.z - __bfloat162float(H.h[2]));
        H.h[3] = __float2bfloat16(f.w); L.h[3] = __float2bfloat16(f.w - __bfloat162float(H.h[3]));
        *(uint2*)(g_hi + gb + e) = H.u;
        *(uint2*)(g_lo + gb + e) = L.u;
    }
    #pragma unroll
    for (int off = 16; off > 0; off >>= 1)
        s += __shfl_xor_sync(0xffffffffu, s, off);
    if (lane == 0) g_sq[row] = s;

    __syncthreads();
    atomicAdd(&g_colsum[t], s_col[t]);
    atomicAdd(&g_colsum[t + 256], s_col[t + 256]);
}

// ---------------- bandwidth + exp constant (256 threads) -------------------
__global__ void k_prep() {
    __shared__ double sh1[8], sh2[8];
    int t = threadIdx.x;
    int warp = t >> 5, lane = t & 31;
    double a = 0.0, b = 0.0;
    const float4* sq4 = (const float4*)g_sq;
    #pragma unroll
    for (int i = 0; i < 8; i++) {
        float4 f = sq4[t + 256 * i];
        a += (double)f.x + (double)f.y + (double)f.z + (double)f.w;
    }
    #pragma unroll
    for (int i = 0; i < 2; i++) {
        double v = (double)g_colsum[t + 256 * i];
        b += v * v;
    }
    #pragma unroll
    for (int off = 16; off > 0; off >>= 1) {
        a += __shfl_xor_sync(0xffffffffu, a, off);
        b += __shfl_xor_sync(0xffffffffu, b, off);
    }
    if (lane == 0) { sh1[warp] = a; sh2[warp] = b; }
    __syncthreads();
    if (t == 0) {
        double A = 0.0, B = 0.0;
        #pragma unroll
        for (int w = 0; w < 8; w++) { A += sh1[w]; B += sh2[w]; }
        double n = (double)NTOT;
        double sum_l2 = 2.0 * n * A - 2.0 * B;
        double bw = sum_l2 / (n * n - n);
        g_c = (float)(1.4426950408889634 / (4.0 * bw + 1e-8));
    }
}

// ---------------- main: HMMA gram + fused RBF epilogue ---------------------
__global__ void __launch_bounds__(256, 2) k_main() {
    extern __shared__ char smem[];
    float* s_sqi = (float*)smem;          // [128] = g_sq * cst
    float* s_sqj = (float*)(smem + 512);  // [128] = g_sq * cst
    uint32_t sb = smem_u32(smem);
    int tid = threadIdx.x;
    int wid = tid >> 5;
    int lid = tid & 31;
    int wm = wid & 3, wn = wid >> 2;      // warp grid 4 x 2 (m x n)

    // triangular tile decode: I <= J
    int beta = blockIdx.x;
    int Ip = (int)((sqrtf(8.0f * (float)beta + 1.0f) - 1.0f) * 0.5f);
    while ((Ip + 1) * (Ip + 2) / 2 <= beta) Ip++;
    while (Ip * (Ip + 1) / 2 > beta) Ip--;
    int Jp = beta - Ip * (Ip + 1) / 2;
    int I = Jp, J = Ip;
    int row0 = I * BM, col0 = J * BM;

    float cst = g_c;
    if (tid < BM)       s_sqi[tid] = g_sq[row0 + tid] * cst;
    else                s_sqj[tid - BM] = g_sq[col0 + tid - BM] * cst;

    // --- async chunk loader: chunk c -> buffer c%3: Ahi, Alo, Bhi, Blo -----
    auto load_chunk = [&](int c) {
        uint32_t base = sb + SM_BUF + (c % 3) * BUFB;
        int k0 = c * KC;
        #pragma unroll
        for (int p = 0; p < 8; p++) {
            int q = tid + 256 * p;            // 0..2047 16B-segments
            int arr = q >> 9;                 // 0..3
            int s = q & 511;
            int r = s >> 2, c4 = s & 3;
            uint32_t sw = swz64(r * 64 + c4 * 16);
            size_t eo;
            if (arr < 2) eo = (size_t)(row0 + r) * DDIM + k0 + c4 * 8;
            else         eo = (size_t)(col0 + r) * DDIM + k0 + c4 * 8;
            const __nv_bfloat16* gsrc = ((arr & 1) == 0) ? g_hi : g_lo;
            cp_async16(base + arr * TILEB + sw, gsrc + eo);
        }
        CP_COMMIT();
    };

    float acc[2][8][4];
    #pragma unroll
    for (int mt = 0; mt < 2; mt++)
        #pragma unroll
        for (int nt = 0; nt < 8; nt++)
            #pragma unroll
            for (int k = 0; k < 4; k++) acc[mt][nt][k] = 0.f;

    load_chunk(0);
    load_chunk(1);

    int fr = lid & 15;                       // row within 16-row group
    uint32_t fcol = ((lid >> 4) & 1) * 16;   // 16B k-half

    for (int c = 0; c < NCH; c++) {
        if (c < NCH - 1) CP_WAIT1(); else CP_WAIT0();
        __syncthreads();
        // issue next-next load into buf (c+2)%3 == (c-1)%3 (all warps past c-1)
        if (c + 2 < NCH) load_chunk(c + 2);

        uint32_t base = sb + SM_BUF + (c % 3) * BUFB;
        #pragma unroll
        for (int kk = 0; kk < 2; kk++) {
            uint32_t kb = kk * 32 + fcol;
            uint32_t ah[2][4], al[2][4];
            #pragma unroll
            for (int mt = 0; mt < 2; mt++) {
                uint32_t sw = swz64((wm * 32 + mt * 16 + fr) * 64 + kb);
                ldsm_x4(ah[mt][0], ah[mt][1], ah[mt][2], ah[mt][3], base + sw);
                ldsm_x4(al[mt][0], al[mt][1], al[mt][2], al[mt][3], base + TILEB + sw);
            }
            #pragma unroll
            for (int p = 0; p < 4; p++) {
                uint32_t sw = swz64((wn * 64 + p * 16 + fr) * 64 + kb);
                uint32_t bh0, bh1, bh2, bh3, bl0, bl1, bl2, bl3;
                ldsm_x4(bh0, bh1, bh2, bh3, base + 2 * TILEB + sw);
                ldsm_x4(bl0, bl1, bl2, bl3, base + 3 * TILEB + sw);
                // cycle 4 independent accumulators per split term:
                // same-acc reuse spacing = 4 MMAs (breaks RAW chains)
                mma16816(acc[0][2 * p],     ah[0], bh0, bh2);
                mma16816(acc[1][2 * p],     ah[1], bh0, bh2);
                mma16816(acc[0][2 * p + 1], ah[0], bh1, bh3);
                mma16816(acc[1][2 * p + 1], ah[1], bh1, bh3);
                mma16816(acc[0][2 * p],     ah[0], bl0, bl2);
                mma16816(acc[1][2 * p],     ah[1], bl0, bl2);
                mma16816(acc[0][2 * p + 1], ah[0], bl1, bl3);
                mma16816(acc[1][2 * p + 1], ah[1], bl1, bl3);
                mma16816(acc[0][2 * p],     al[0], bh0, bh2);
                mma16816(acc[1][2 * p],     al[1], bh0, bh2);
                mma16816(acc[0][2 * p + 1], al[0], bh1, bh3);
                mma16816(acc[1][2 * p + 1], al[1], bh1, bh3);
            }
        }
    }

    // ---- epilogue: acc -> t = min(2c*dot - (sqi+sqj)*c, 0); b=2^t;
    //               fs += b + b^2 + b^4 + b^8 + b^16
    float c2 = 2.0f * cst;
    int g = lid >> 2, t4 = lid & 3;
    double accd = 0.0;
    #pragma unroll
    for (int mt = 0; mt < 2; mt++) {
        float si0 = s_sqi[wm * 32 + mt * 16 + g];
        float si1 = s_sqi[wm * 32 + mt * 16 + g + 8];
        float fs = 0.f;
        #pragma unroll
        for (int nt = 0; nt < 8; nt++) {
            float sj0 = s_sqj[wn * 64 + nt * 8 + 2 * t4];
            float sj1 = s_sqj[wn * 64 + nt * 8 + 2 * t4 + 1];
            #pragma unroll
            for (int k = 0; k < 4; k++) {
                float si = (k < 2) ? si0 : si1;
                float sj = (k & 1) ? sj1 : sj0;
                float t = fminf(fmaf(c2, acc[mt][nt][k], -(si + sj)), 0.0f);
                float b1 = ex2_approx(t);
                float p2 = b1 * b1;
                float p4 = p2 * p2;
                float p8 = p4 * p4;
                float p16 = p8 * p8;
                fs += (b1 + p2) + (p4 + p8) + p16;
            }
        }
        accd += (double)fs;
    }

    __shared__ double sred[256];
    sred[tid] = accd;
    __syncthreads();
    for (int s = 128; s > 0; s >>= 1) {
        if (tid < s) sred[tid] += sred[tid + s];
        __syncthreads();
    }
    if (tid == 0) {
        double v = sred[0] * ((I == J) ? 1.0 : 2.0);
        int bin = (J < GBLK / 2) ? 0 : ((I >= GBLK / 2) ? 1 : 2);
        atomicAdd(&g_bins[bin], v);
    }
}

// ---- finalize + reset accumulator state for the next graph replay ---------
__global__ void k_final(float* out) {
    int t = threadIdx.x;
    if (t == 0) {
        double ns2 = (double)NS * (double)NS;
        out[0] = (float)((g_bins[0] + g_bins[1] - g_bins[2]) / ns2);
    }
    __syncthreads();
    if (t < 3) g_bins[t] = 0.0;
    g_colsum[t] = 0.f;
    g_colsum[t + 256] = 0.f;
}

extern "C" void kernel_launch(void* const* d_in, const int* in_sizes, int n_in,
                              void* d_out, int out_size) {
    const float* src = (const float*)d_in[0];
    const float* tgt = (const float*)d_in[1];
    float* out = (float*)d_out;

    cudaFuncSetAttribute(k_main, cudaFuncAttributeMaxDynamicSharedMemorySize,
                         SMEM_DYN);
    k_convert<<<NTOT / 8, 256>>>(src, tgt);
    k_prep<<<1, 256>>>();
    k_main<<<NBLK, 256, SMEM_DYN>>>();
    k_final<<<1, 256>>>(out);
}

// round 6
// speedup vs baseline: 4.3186x; 1.5086x over previous
#include <cuda_runtime.h>
#include <cuda_bf16.h>
#include <math.h>
#include <stdint.h>

// ---------------------------------------------------------------------------
// MMDLoss: source (4096,512) f32, target (4096,512) f32 -> scalar f32
//
// Gram in SINGLE bf16 on mma.sync.m16n8k16 (HMMA). Row sq-norms computed from
// the bf16-rounded values so the diagonal l2 is exactly ~0 (consistent
// geometry); mean-averaging kills the per-element bf16 noise (~2e-5 final).
// Triangular 128x128 tiles, KC=64 chunks (SW128), 3-stage cp.async pipeline.
// Bandwidth closed-form: sum(l2) = 2N*sum(sq) - 2*||colsum||^2.
// 5-bandwidth RBF collapses to b + b^2 + b^4 + b^8 + b^16, b = exp(-l2/(4bw)).
// ---------------------------------------------------------------------------

#define NS    4096
#define NTOT  8192
#define DDIM  512
#define BM    128
#define GBLK  64
#define NBLK  2080            // 64*65/2 triangular tile pairs
#define KC    64              // K elements per chunk (64 bf16 = 128B row)
#define NCH   8               // 512/64

#define TILEB 16384           // 128 rows * 128 bytes
#define BUFB  (2 * TILEB)     // Ahi, Bhi = 32KB
#define SM_BUF 1024
#define SMEM_DYN (SM_BUF + 3 * BUFB)   // 99328 bytes -> 2 CTAs/SM (regs bind)

__device__ __nv_bfloat16 g_hi[NTOT * DDIM];   // 8 MB
__device__ float  g_sq[NTOT];       // sq of bf16-rounded rows
__device__ float  g_colsum[DDIM];   // zero-init at load; k_final re-zeroes
__device__ float  g_c;              // log2(e) / (4*bw + eps)
__device__ double g_bins[3];        // Sxx, Syy, Scross; k_final re-zeroes

// ------------------------------ PTX helpers -------------------------------
__device__ __forceinline__ uint32_t smem_u32(const void* p) {
    uint32_t a;
    asm("{ .reg .u64 t; cvta.to.shared.u64 t, %1; cvt.u32.u64 %0, t; }"
        : "=r"(a) : "l"(p));
    return a;
}
__device__ __forceinline__ void cp_async16(uint32_t sa, const void* g) {
    asm volatile("cp.async.cg.shared.global [%0], [%1], 16;"
                 :: "r"(sa), "l"(g) : "memory");
}
#define CP_COMMIT() asm volatile("cp.async.commit_group;" ::: "memory")
#define CP_WAIT1()  asm volatile("cp.async.wait_group 1;" ::: "memory")
#define CP_WAIT0()  asm volatile("cp.async.wait_group 0;" ::: "memory")

__device__ __forceinline__ void ldsm_x4(uint32_t& r0, uint32_t& r1,
                                        uint32_t& r2, uint32_t& r3, uint32_t a) {
    asm volatile("ldmatrix.sync.aligned.m8n8.x4.shared.b16 {%0,%1,%2,%3}, [%4];"
                 : "=r"(r0), "=r"(r1), "=r"(r2), "=r"(r3) : "r"(a));
}
__device__ __forceinline__ void mma16816(float* c, const uint32_t* a,
                                         uint32_t b0, uint32_t b1) {
    asm volatile(
        "mma.sync.aligned.m16n8k16.row.col.f32.bf16.bf16.f32 "
        "{%0,%1,%2,%3}, {%4,%5,%6,%7}, {%8,%9}, {%0,%1,%2,%3};"
        : "+f"(c[0]), "+f"(c[1]), "+f"(c[2]), "+f"(c[3])
        : "r"(a[0]), "r"(a[1]), "r"(a[2]), "r"(a[3]), "r"(b0), "r"(b1));
}
__device__ __forceinline__ float ex2_approx(float x) {
    float r;
    asm("ex2.approx.ftz.f32 %0, %1;" : "=f"(r) : "f"(x));
    return r;
}
// SW128 swizzle for 128-byte rows (atom: 8 rows x 128B)
__device__ __forceinline__ uint32_t swz(uint32_t bo) {
    return bo ^ ((bo >> 3) & 0x70);
}

// --- convert f32 -> bf16 + row sq norms (of bf16) + fused column sums ------
__global__ void k_convert(const float* __restrict__ src, const float* __restrict__ tgt) {
    __shared__ float s_col[DDIM];
    int t = threadIdx.x;
    s_col[t] = 0.f; s_col[t + 256] = 0.f;
    __syncthreads();

    int warp = t >> 5;
    int lane = t & 31;
    int row  = blockIdx.x * 8 + warp;
    const float* p = (row < NS) ? (src + (size_t)row * DDIM)
                                : (tgt + (size_t)(row - NS) * DDIM);
    size_t gb = (size_t)row * DDIM;
    float s = 0.f;
    #pragma unroll
    for (int v = 0; v < 4; v++) {
        int e = (lane + v * 32) * 4;
        float4 f = *(const float4*)(p + e);
        atomicAdd(&s_col[e + 0], f.x);
        atomicAdd(&s_col[e + 1], f.y);
        atomicAdd(&s_col[e + 2], f.z);
        atomicAdd(&s_col[e + 3], f.w);
        union { __nv_bfloat16 h[4]; uint2 u; } H;
        H.h[0] = __float2bfloat16(f.x);
        H.h[1] = __float2bfloat16(f.y);
        H.h[2] = __float2bfloat16(f.z);
        H.h[3] = __float2bfloat16(f.w);
        // sq from the bf16-rounded values -> diagonal l2 ~ 0 exactly
        float r0 = __bfloat162float(H.h[0]);
        float r1 = __bfloat162float(H.h[1]);
        float r2 = __bfloat162float(H.h[2]);
        float r3 = __bfloat162float(H.h[3]);
        s = fmaf(r0, r0, s); s = fmaf(r1, r1, s);
        s = fmaf(r2, r2, s); s = fmaf(r3, r3, s);
        *(uint2*)(g_hi + gb + e) = H.u;
    }
    #pragma unroll
    for (int off = 16; off > 0; off >>= 1)
        s += __shfl_xor_sync(0xffffffffu, s, off);
    if (lane == 0) g_sq[row] = s;

    __syncthreads();
    atomicAdd(&g_colsum[t], s_col[t]);
    atomicAdd(&g_colsum[t + 256], s_col[t + 256]);
}

// ---------------- bandwidth + exp constant (256 threads) -------------------
__global__ void k_prep() {
    __shared__ double sh1[8], sh2[8];
    int t = threadIdx.x;
    int warp = t >> 5, lane = t & 31;
    double a = 0.0, b = 0.0;
    const float4* sq4 = (const float4*)g_sq;
    #pragma unroll
    for (int i = 0; i < 8; i++) {
        float4 f = sq4[t + 256 * i];
        a += (double)f.x + (double)f.y + (double)f.z + (double)f.w;
    }
    #pragma unroll
    for (int i = 0; i < 2; i++) {
        double v = (double)g_colsum[t + 256 * i];
        b += v * v;
    }
    #pragma unroll
    for (int off = 16; off > 0; off >>= 1) {
        a += __shfl_xor_sync(0xffffffffu, a, off);
        b += __shfl_xor_sync(0xffffffffu, b, off);
    }
    if (lane == 0) { sh1[warp] = a; sh2[warp] = b; }
    __syncthreads();
    if (t == 0) {
        double A = 0.0, B = 0.0;
        #pragma unroll
        for (int w = 0; w < 8; w++) { A += sh1[w]; B += sh2[w]; }
        double n = (double)NTOT;
        double sum_l2 = 2.0 * n * A - 2.0 * B;
        double bw = sum_l2 / (n * n - n);
        g_c = (float)(1.4426950408889634 / (4.0 * bw + 1e-8));
    }
}

// ---------------- main: HMMA gram + fused RBF epilogue ---------------------
__global__ void __launch_bounds__(256, 2) k_main() {
    extern __shared__ char smem[];
    float* s_sqi = (float*)smem;          // [128] = g_sq * cst
    float* s_sqj = (float*)(smem + 512);  // [128] = g_sq * cst
    uint32_t sb = smem_u32(smem);
    int tid = threadIdx.x;
    int wid = tid >> 5;
    int lid = tid & 31;
    int wm = wid & 3, wn = wid >> 2;      // warp grid 4 x 2 (m x n)

    // triangular tile decode: I <= J
    int beta = blockIdx.x;
    int Ip = (int)((sqrtf(8.0f * (float)beta + 1.0f) - 1.0f) * 0.5f);
    while ((Ip + 1) * (Ip + 2) / 2 <= beta) Ip++;
    while (Ip * (Ip + 1) / 2 > beta) Ip--;
    int Jp = beta - Ip * (Ip + 1) / 2;
    int I = Jp, J = Ip;
    int row0 = I * BM, col0 = J * BM;

    float cst = g_c;
    if (tid < BM)       s_sqi[tid] = g_sq[row0 + tid] * cst;
    else                s_sqj[tid - BM] = g_sq[col0 + tid - BM] * cst;

    // --- async chunk loader: chunk c -> buffer c%3: Ahi, Bhi ---------------
    auto load_chunk = [&](int c) {
        uint32_t base = sb + SM_BUF + (c % 3) * BUFB;
        int k0 = c * KC;
        #pragma unroll
        for (int p = 0; p < 8; p++) {
            int q = tid + 256 * p;            // 0..2047 16B-segments
            int arr = q >> 10;                // 0: A, 1: B
            int s = q & 1023;
            int r = s >> 3, c8 = s & 7;
            uint32_t sw = swz(r * 128 + c8 * 16);
            size_t eo = (size_t)((arr ? col0 : row0) + r) * DDIM + k0 + c8 * 8;
            cp_async16(base + arr * TILEB + sw, g_hi + eo);
        }
        CP_COMMIT();
    };

    float acc[2][8][4];
    #pragma unroll
    for (int mt = 0; mt < 2; mt++)
        #pragma unroll
        for (int nt = 0; nt < 8; nt++)
            #pragma unroll
            for (int k = 0; k < 4; k++) acc[mt][nt][k] = 0.f;

    load_chunk(0);
    load_chunk(1);

    int fr = lid & 15;                       // row within 16-row group
    uint32_t fcol = ((lid >> 4) & 1) * 16;   // 16B k-half

    for (int c = 0; c < NCH; c++) {
        if (c < NCH - 1) CP_WAIT1(); else CP_WAIT0();
        __syncthreads();
        // issue next-next load into buf (c+2)%3 == (c-1)%3 (all warps past c-1)
        if (c + 2 < NCH) load_chunk(c + 2);

        uint32_t base = sb + SM_BUF + (c % 3) * BUFB;
        #pragma unroll
        for (int kk = 0; kk < 4; kk++) {
            uint32_t kb = kk * 32 + fcol;
            uint32_t ah[2][4];
            #pragma unroll
            for (int mt = 0; mt < 2; mt++) {
                uint32_t sw = swz((wm * 32 + mt * 16 + fr) * 128 + kb);
                ldsm_x4(ah[mt][0], ah[mt][1], ah[mt][2], ah[mt][3], base + sw);
            }
            #pragma unroll
            for (int p = 0; p < 4; p++) {
                uint32_t sw = swz((wn * 64 + p * 16 + fr) * 128 + kb);
                uint32_t bh0, bh1, bh2, bh3;
                ldsm_x4(bh0, bh1, bh2, bh3, base + TILEB + sw);
                // 4 independent accumulators -> RAW spacing 4
                mma16816(acc[0][2 * p],     ah[0], bh0, bh2);
                mma16816(acc[1][2 * p],     ah[1], bh0, bh2);
                mma16816(acc[0][2 * p + 1], ah[0], bh1, bh3);
                mma16816(acc[1][2 * p + 1], ah[1], bh1, bh3);
            }
        }
    }

    // ---- epilogue: acc -> t = min(2c*dot - (sqi+sqj)*c, 0); b=2^t;
    //               fs += b + b^2 + b^4 + b^8 + b^16
    float c2 = 2.0f * cst;
    int g = lid >> 2, t4 = lid & 3;
    double accd = 0.0;
    #pragma unroll
    for (int mt = 0; mt < 2; mt++) {
        float si0 = s_sqi[wm * 32 + mt * 16 + g];
        float si1 = s_sqi[wm * 32 + mt * 16 + g + 8];
        float fs = 0.f;
        #pragma unroll
        for (int nt = 0; nt < 8; nt++) {
            float sj0 = s_sqj[wn * 64 + nt * 8 + 2 * t4];
            float sj1 = s_sqj[wn * 64 + nt * 8 + 2 * t4 + 1];
            #pragma unroll
            for (int k = 0; k < 4; k++) {
                float si = (k < 2) ? si0 : si1;
                float sj = (k & 1) ? sj1 : sj0;
                float t = fminf(fmaf(c2, acc[mt][nt][k], -(si + sj)), 0.0f);
                float b1 = ex2_approx(t);
                float p2 = b1 * b1;
                float p4 = p2 * p2;
                float p8 = p4 * p4;
                float p16 = p8 * p8;
                fs += (b1 + p2) + (p4 + p8) + p16;
            }
        }
        accd += (double)fs;
    }

    __shared__ double sred[256];
    sred[tid] = accd;
    __syncthreads();
    for (int s = 128; s > 0; s >>= 1) {
        if (tid < s) sred[tid] += sred[tid + s];
        __syncthreads();
    }
    if (tid == 0) {
        double v = sred[0] * ((I == J) ? 1.0 : 2.0);
        int bin = (J < GBLK / 2) ? 0 : ((I >= GBLK / 2) ? 1 : 2);
        atomicAdd(&g_bins[bin], v);
    }
}

// ---- finalize + reset accumulator state for the next graph replay ---------
__global__ void k_final(float* out) {
    int t = threadIdx.x;
    if (t == 0) {
        double ns2 = (double)NS * (double)NS;
        out[0] = (float)((g_bins[0] + g_bins[1] - g_bins[2]) / ns2);
    }
    __syncthreads();
    if (t < 3) g_bins[t] = 0.0;
    g_colsum[t] = 0.f;
    g_colsum[t + 256] = 0.f;
}

extern "C" void kernel_launch(void* const* d_in, const int* in_sizes, int n_in,
                              void* d_out, int out_size) {
    const float* src = (const float*)d_in[0];
    const float* tgt = (const float*)d_in[1];
    float* out = (float*)d_out;

    cudaFuncSetAttribute(k_main, cudaFuncAttributeMaxDynamicSharedMemorySize,
                         SMEM_DYN);
    k_convert<<<NTOT / 8, 256>>>(src, tgt);
    k_prep<<<1, 256>>>();
    k_main<<<NBLK, 256, SMEM_DYN>>>();
    k_final<<<1, 256>>>(out);
}

// round 8
// speedup vs baseline: 5.6495x; 1.3082x over previous
#include <cuda_runtime.h>
#include <cuda_bf16.h>
#include <math.h>
#include <stdint.h>

// ---------------------------------------------------------------------------
// MMDLoss: source (4096,512) f32, target (4096,512) f32 -> scalar f32
//
// Gram in single bf16 on mma.sync.m16n8k16 (HMMA), sq-norms from bf16-rounded
// rows (consistent geometry -> exact-ish diagonal). CTA tile 128x256, warp
// tile 64x64 (2x4 warp grid) to halve SMEM crossbar traffic per MAC.
// 528 coarse 256x256 triangular pairs x 2 half-CTAs = 1056 CTAs.
// Bandwidth closed-form: sum(l2) = 2N*sum(sq) - 2*||colsum||^2.
// 5-bandwidth RBF collapses to b + b^2 + b^4 + b^8 + b^16, b = exp(-l2/(4bw)).
// ---------------------------------------------------------------------------

#define NS    4096
#define NTOT  8192
#define DDIM  512
#define CGB   32              // coarse blocks of 256
#define NCOARSE 528           // 32*33/2
#define NBLK  (2 * NCOARSE)   // 1056 CTAs
#define KC    64              // K elements per chunk (128B row)
#define NCH   8               // 512/64

#define TILEA 16384           // 128 rows * 128B
#define TILEB_SZ 32768        // 256 rows * 128B
#define BUFB  (TILEA + TILEB_SZ)          // 48KB per stage
#define SMEM_DYN (1024 + 3 * BUFB)        // ~148.5 KB -> 1 CTA/SM

__device__ __nv_bfloat16 g_hi[NTOT * DDIM];   // 8 MB
__device__ float  g_sq[NTOT];       // sq of bf16-rounded rows
__device__ float  g_colsum[DDIM];   // zero-init; k_final re-zeroes
__device__ float  g_c;              // log2(e) / (4*bw + eps)
__device__ double g_bins[3];        // Sxx, Syy, Scross; k_final re-zeroes

// ------------------------------ PTX helpers -------------------------------
__device__ __forceinline__ uint32_t smem_u32(const void* p) {
    uint32_t a;
    asm("{ .reg .u64 t; cvta.to.shared.u64 t, %1; cvt.u32.u64 %0, t; }"
        : "=r"(a) : "l"(p));
    return a;
}
__device__ __forceinline__ void cp_async16(uint32_t sa, const void* g) {
    asm volatile("cp.async.cg.shared.global [%0], [%1], 16;"
                 :: "r"(sa), "l"(g) : "memory");
}
#define CP_COMMIT() asm volatile("cp.async.commit_group;" ::: "memory")
#define CP_WAIT1()  asm volatile("cp.async.wait_group 1;" ::: "memory")
#define CP_WAIT0()  asm volatile("cp.async.wait_group 0;" ::: "memory")

__device__ __forceinline__ void ldsm_x4(uint32_t& r0, uint32_t& r1,
                                        uint32_t& r2, uint32_t& r3, uint32_t a) {
    asm volatile("ldmatrix.sync.aligned.m8n8.x4.shared.b16 {%0,%1,%2,%3}, [%4];"
                 : "=r"(r0), "=r"(r1), "=r"(r2), "=r"(r3) : "r"(a));
}
__device__ __forceinline__ void mma16816(float* c, const uint32_t* a,
                                         uint32_t b0, uint32_t b1) {
    asm volatile(
        "mma.sync.aligned.m16n8k16.row.col.f32.bf16.bf16.f32 "
        "{%0,%1,%2,%3}, {%4,%5,%6,%7}, {%8,%9}, {%0,%1,%2,%3};"
        : "+f"(c[0]), "+f"(c[1]), "+f"(c[2]), "+f"(c[3])
        : "r"(a[0]), "r"(a[1]), "r"(a[2]), "r"(a[3]), "r"(b0), "r"(b1));
}
__device__ __forceinline__ float ex2_approx(float x) {
    float r;
    asm("ex2.approx.ftz.f32 %0, %1;" : "=f"(r) : "f"(x));
    return r;
}
// SW128 swizzle for 128-byte rows (atom: 8 rows x 128B)
__device__ __forceinline__ uint32_t swz(uint32_t bo) {
    return bo ^ ((bo >> 3) & 0x70);
}

// --- convert f32 -> bf16 + row sq norms (of bf16) + fused column sums ------
__global__ void k_convert(const float* __restrict__ src, const float* __restrict__ tgt) {
    __shared__ float s_col[DDIM];
    int t = threadIdx.x;
    s_col[t] = 0.f; s_col[t + 256] = 0.f;
    __syncthreads();

    int warp = t >> 5;
    int lane = t & 31;
    int row  = blockIdx.x * 8 + warp;
    const float* p = (row < NS) ? (src + (size_t)row * DDIM)
                                : (tgt + (size_t)(row - NS) * DDIM);
    size_t gb = (size_t)row * DDIM;
    float s = 0.f;
    #pragma unroll
    for (int v = 0; v < 4; v++) {
        int e = (lane + v * 32) * 4;
        float4 f = *(const float4*)(p + e);
        atomicAdd(&s_col[e + 0], f.x);
        atomicAdd(&s_col[e + 1], f.y);
        atomicAdd(&s_col[e + 2], f.z);
        atomicAdd(&s_col[e + 3], f.w);
        union { __nv_bfloat16 h[4]; uint2 u; } H;
        H.h[0] = __float2bfloat16(f.x);
        H.h[1] = __float2bfloat16(f.y);
        H.h[2] = __float2bfloat16(f.z);
        H.h[3] = __float2bfloat16(f.w);
        float r0 = __bfloat162float(H.h[0]);
        float r1 = __bfloat162float(H.h[1]);
        float r2 = __bfloat162float(H.h[2]);
        float r3 = __bfloat162float(H.h[3]);
        s = fmaf(r0, r0, s); s = fmaf(r1, r1, s);
        s = fmaf(r2, r2, s); s = fmaf(r3, r3, s);
        *(uint2*)(g_hi + gb + e) = H.u;
    }
    #pragma unroll
    for (int off = 16; off > 0; off >>= 1)
        s += __shfl_xor_sync(0xffffffffu, s, off);
    if (lane == 0) g_sq[row] = s;

    __syncthreads();
    atomicAdd(&g_colsum[t], s_col[t]);
    atomicAdd(&g_colsum[t + 256], s_col[t + 256]);
}

// ---------------- bandwidth + exp constant (256 threads) -------------------
__global__ void k_prep() {
    __shared__ double sh1[8], sh2[8];
    int t = threadIdx.x;
    int warp = t >> 5, lane = t & 31;
    double a = 0.0, b = 0.0;
    const float4* sq4 = (const float4*)g_sq;
    #pragma unroll
    for (int i = 0; i < 8; i++) {
        float4 f = sq4[t + 256 * i];
        a += (double)f.x + (double)f.y + (double)f.z + (double)f.w;
    }
    #pragma unroll
    for (int i = 0; i < 2; i++) {
        double v = (double)g_colsum[t + 256 * i];
        b += v * v;
    }
    #pragma unroll
    for (int off = 16; off > 0; off >>= 1) {
        a += __shfl_xor_sync(0xffffffffu, a, off);
        b += __shfl_xor_sync(0xffffffffu, b, off);
    }
    if (lane == 0) { sh1[warp] = a; sh2[warp] = b; }
    __syncthreads();
    if (t == 0) {
        double A = 0.0, B = 0.0;
        #pragma unroll
        for (int w = 0; w < 8; w++) { A += sh1[w]; B += sh2[w]; }
        double n = (double)NTOT;
        double sum_l2 = 2.0 * n * A - 2.0 * B;
        double bw = sum_l2 / (n * n - n);
        g_c = (float)(1.4426950408889634 / (4.0 * bw + 1e-8));
    }
}

// ---------------- main: HMMA gram + fused RBF epilogue ---------------------
__global__ void __launch_bounds__(256, 1) k_main() {
    __shared__ float s_sqi[128];
    __shared__ float s_sqj[256];
    __shared__ double sred[256];
    extern __shared__ char dsm[];
    uint32_t sb = (smem_u32(dsm) + 1023) & ~1023u;   // 1KB-align buffers

    int tid = threadIdx.x;
    int wid = tid >> 5;
    int lid = tid & 31;
    int wm = wid & 1, wn = wid >> 1;      // warp grid 2(m) x 4(n), 64x64 tiles

    // coarse triangular decode over 32 blocks of 256: CI <= CJ
    int beta = blockIdx.x >> 1;
    int h = blockIdx.x & 1;
    int Ip = (int)((sqrtf(8.0f * (float)beta + 1.0f) - 1.0f) * 0.5f);
    while ((Ip + 1) * (Ip + 2) / 2 <= beta) Ip++;
    while (Ip * (Ip + 1) / 2 > beta) Ip--;
    int Jp = beta - Ip * (Ip + 1) / 2;
    int CI = Jp, CJ = Ip;                 // CI <= CJ
    int row0 = CI * 256 + h * 128;        // 128 rows
    int col0 = CJ * 256;                  // 256 cols

    float cst = g_c;
    if (tid < 128) s_sqi[tid] = g_sq[row0 + tid] * cst;
    s_sqj[tid] = g_sq[col0 + tid] * cst;

    // --- async chunk loader: chunk c -> buffer c%3: A(128x128B), B(256x128B)
    auto load_chunk = [&](int c) {
        uint32_t base = sb + (c % 3) * BUFB;
        int k0 = c * KC;
        #pragma unroll
        for (int p = 0; p < 12; p++) {
            int q = tid + 256 * p;            // 0..3071 16B-segments
            int isB = (q >= 1024);
            int s = isB ? (q - 1024) : q;
            int r = s >> 3, c8 = s & 7;
            uint32_t sw = swz(r * 128 + c8 * 16);
            size_t eo = (size_t)((isB ? col0 : row0) + r) * DDIM + k0 + c8 * 8;
            cp_async16(base + (isB ? TILEA : 0) + sw, g_hi + eo);
        }
        CP_COMMIT();
    };

    float acc[4][8][4];                   // 4 m16-blocks x 8 n8-blocks x 4
    #pragma unroll
    for (int mt = 0; mt < 4; mt++)
        #pragma unroll
        for (int nt = 0; nt < 8; nt++)
            #pragma unroll
            for (int k = 0; k < 4; k++) acc[mt][nt][k] = 0.f;

    load_chunk(0);
    load_chunk(1);

    int fr = lid & 15;                       // row within 16-row group
    uint32_t fcol = ((lid >> 4) & 1) * 16;   // 16B k-half

    for (int c = 0; c < NCH; c++) {
        if (c < NCH - 1) CP_WAIT1(); else CP_WAIT0();
        __syncthreads();
        if (c + 2 < NCH) load_chunk(c + 2);  // buf (c+2)%3 == (c-1)%3

        uint32_t base = sb + (c % 3) * BUFB;
        #pragma unroll
        for (int kk = 0; kk < 4; kk++) {
            uint32_t kb = kk * 32 + fcol;
            uint32_t ah[4][4];
            #pragma unroll
            for (int mt = 0; mt < 4; mt++) {
                uint32_t sw = swz((wm * 64 + mt * 16 + fr) * 128 + kb);
                ldsm_x4(ah[mt][0], ah[mt][1], ah[mt][2], ah[mt][3], base + sw);
            }
            #pragma unroll
            for (int p = 0; p < 4; p++) {
                uint32_t sw = swz((wn * 64 + p * 16 + fr) * 128 + kb);
                uint32_t bh0, bh1, bh2, bh3;
                ldsm_x4(bh0, bh1, bh2, bh3, base + TILEA + sw);
                #pragma unroll
                for (int mt = 0; mt < 4; mt++) {
                    mma16816(acc[mt][2 * p],     ah[mt], bh0, bh2);
                    mma16816(acc[mt][2 * p + 1], ah[mt], bh1, bh3);
                }
            }
        }
    }

    // ---- epilogue: acc -> t = min(2c*dot - (sqi+sqj)*c, 0); b=2^t;
    //               fs += b + b^2 + b^4 + b^8 + b^16
    float c2 = 2.0f * cst;
    int g = lid >> 2, t4 = lid & 3;
    double accd = 0.0;
    #pragma unroll
    for (int mt = 0; mt < 4; mt++) {
        float si0 = s_sqi[wm * 64 + mt * 16 + g];
        float si1 = s_sqi[wm * 64 + mt * 16 + g + 8];
        float fs = 0.f;
        #pragma unroll
        for (int nt = 0; nt < 8; nt++) {
            float sj0 = s_sqj[wn * 64 + nt * 8 + 2 * t4];
            float sj1 = s_sqj[wn * 64 + nt * 8 + 2 * t4 + 1];
            #pragma unroll
            for (int k = 0; k < 4; k++) {
                float si = (k < 2) ? si0 : si1;
                float sj = (k & 1) ? sj1 : sj0;
                float t = fminf(fmaf(c2, acc[mt][nt][k], -(si + sj)), 0.0f);
                float b1 = ex2_approx(t);
                float p2 = b1 * b1;
                float p4 = p2 * p2;
                float p8 = p4 * p4;
                float p16 = p8 * p8;
                fs += (b1 + p2) + (p4 + p8) + p16;
            }
        }
        accd += (double)fs;
    }

    sred[tid] = accd;
    __syncthreads();
    for (int s = 128; s > 0; s >>= 1) {
        if (tid < s) sred[tid] += sred[tid + s];
        __syncthreads();
    }
    if (tid == 0) {
        double v = sred[0] * ((CI == CJ) ? 1.0 : 2.0);
        int rhalf = (row0 >= NS), chalf = (col0 >= NS);
        int bin = (rhalf & chalf) ? 1 : ((!rhalf && !chalf) ? 0 : 2);
        atomicAdd(&g_bins[bin], v);
    }
}

// ---- finalize + reset accumulator state for the next graph replay ---------
__global__ void k_final(float* out) {
    int t = threadIdx.x;
    if (t == 0) {
        double ns2 = (double)NS * (double)NS;
        out[0] = (float)((g_bins[0] + g_bins[1] - g_bins[2]) / ns2);
    }
    __syncthreads();
    if (t < 3) g_bins[t] = 0.0;
    g_colsum[t] = 0.f;
    g_colsum[t + 256] = 0.f;
}

extern "C" void kernel_launch(void* const* d_in, const int* in_sizes, int n_in,
                              void* d_out, int out_size) {
    const float* src = (const float*)d_in[0];
    const float* tgt = (const float*)d_in[1];
    float* out = (float*)d_out;

    cudaFuncSetAttribute(k_main, cudaFuncAttributeMaxDynamicSharedMemorySize,
                         SMEM_DYN);
    k_convert<<<NTOT / 8, 256>>>(src, tgt);
    k_prep<<<1, 256>>>();
    k_main<<<NBLK, 256, SMEM_DYN>>>();
    k_final<<<1, 256>>>(out);
}

// round 11
// speedup vs baseline: 5.9556x; 1.0542x over previous
#include <cuda_runtime.h>
#include <cuda_bf16.h>
#include <math.h>
#include <stdint.h>

// ---------------------------------------------------------------------------
// MMDLoss: source (4096,512) f32, target (4096,512) f32 -> scalar f32
//
// Gram in single bf16 on mma.sync.m16n8k16 (HMMA), sq-norms from bf16-rounded
// rows. CTA tile 128x256, warp tile 64x64 (2x4 warp grid). PERSISTENT CTAs
// (1/SM): each walks tiles bid, bid+grid, ... with a continuous 3-slot
// cp.async ring that prefetches the next tile's chunks during the current
// tile's tail/epilogue. Warp-shuffle double reduction + global atomics.
// Bandwidth closed-form: sum(l2) = 2N*sum(sq) - 2*||colsum||^2.
// 5-bandwidth RBF collapses to b + b^2 + b^4 + b^8 + b^16, b = exp(-l2/(4bw)).
// ---------------------------------------------------------------------------

#define NS    4096
#define NTOT  8192
#define DDIM  512
#define NCOARSE 528           // 32*33/2 coarse 256x256 triangular pairs
#define NTILES (2 * NCOARSE)  // 1056 work units (128x256 each)
#define KC    64              // K elements per chunk (128B row)
#define NCH   8               // 512/64

#define TILEA 16384           // A: 128 rows * 128B
#define TILEB_SZ 32768        // B: 256 rows * 128B
#define BUFB  (TILEA + TILEB_SZ)          // 48KB per ring slot
#define SMEM_DYN (1024 + 3 * BUFB)        // ~148.5 KB -> 1 CTA/SM

__device__ __nv_bfloat16 g_hi[NTOT * DDIM];   // 8 MB
__device__ float  g_sq[NTOT];       // sq of bf16-rounded rows
__device__ float  g_colsum[DDIM];   // zero-init; k_final re-zeroes
__device__ float  g_c;              // log2(e) / (4*bw + eps)
__device__ double g_bins[3];        // Sxx, Syy, Scross; k_final re-zeroes

// ------------------------------ PTX helpers -------------------------------
__device__ __forceinline__ uint32_t smem_u32(const void* p) {
    uint32_t a;
    asm("{ .reg .u64 t; cvta.to.shared.u64 t, %1; cvt.u32.u64 %0, t; }"
        : "=r"(a) : "l"(p));
    return a;
}
__device__ __forceinline__ void cp_async16(uint32_t sa, const void* g) {
    asm volatile("cp.async.cg.shared.global [%0], [%1], 16;"
                 :: "r"(sa), "l"(g) : "memory");
}
#define CP_COMMIT() asm volatile("cp.async.commit_group;" ::: "memory")
#define CP_WAIT1()  asm volatile("cp.async.wait_group 1;" ::: "memory")
#define CP_WAIT0()  asm volatile("cp.async.wait_group 0;" ::: "memory")

__device__ __forceinline__ void ldsm_x4(uint32_t& r0, uint32_t& r1,
                                        uint32_t& r2, uint32_t& r3, uint32_t a) {
    asm volatile("ldmatrix.sync.aligned.m8n8.x4.shared.b16 {%0,%1,%2,%3}, [%4];"
                 : "=r"(r0), "=r"(r1), "=r"(r2), "=r"(r3) : "r"(a));
}
__device__ __forceinline__ void mma16816(float* c, const uint32_t* a,
                                         uint32_t b0, uint32_t b1) {
    asm volatile(
        "mma.sync.aligned.m16n8k16.row.col.f32.bf16.bf16.f32 "
        "{%0,%1,%2,%3}, {%4,%5,%6,%7}, {%8,%9}, {%0,%1,%2,%3};"
        : "+f"(c[0]), "+f"(c[1]), "+f"(c[2]), "+f"(c[3])
        : "r"(a[0]), "r"(a[1]), "r"(a[2]), "r"(a[3]), "r"(b0), "r"(b1));
}
__device__ __forceinline__ float ex2_approx(float x) {
    float r;
    asm("ex2.approx.ftz.f32 %0, %1;" : "=f"(r) : "f"(x));
    return r;
}
// SW128 swizzle for 128-byte rows (atom: 8 rows x 128B)
__device__ __forceinline__ uint32_t swz(uint32_t bo) {
    return bo ^ ((bo >> 3) & 0x70);
}

// --- convert f32 -> bf16 + row sq norms (of bf16) + fused column sums ------
__global__ void k_convert(const float* __restrict__ src, const float* __restrict__ tgt) {
    __shared__ float s_col[DDIM];
    int t = threadIdx.x;
    s_col[t] = 0.f; s_col[t + 256] = 0.f;
    __syncthreads();

    int warp = t >> 5;
    int lane = t & 31;
    int row  = blockIdx.x * 8 + warp;
    const float* p = (row < NS) ? (src + (size_t)row * DDIM)
                                : (tgt + (size_t)(row - NS) * DDIM);
    size_t gb = (size_t)row * DDIM;
    float s = 0.f;
    #pragma unroll
    for (int v = 0; v < 4; v++) {
        int e = (lane + v * 32) * 4;
        float4 f = *(const float4*)(p + e);
        atomicAdd(&s_col[e + 0], f.x);
        atomicAdd(&s_col[e + 1], f.y);
        atomicAdd(&s_col[e + 2], f.z);
        atomicAdd(&s_col[e + 3], f.w);
        union { __nv_bfloat16 h[4]; uint2 u; } H;
        H.h[0] = __float2bfloat16(f.x);
        H.h[1] = __float2bfloat16(f.y);
        H.h[2] = __float2bfloat16(f.z);
        H.h[3] = __float2bfloat16(f.w);
        float r0 = __bfloat162float(H.h[0]);
        float r1 = __bfloat162float(H.h[1]);
        float r2 = __bfloat162float(H.h[2]);
        float r3 = __bfloat162float(H.h[3]);
        s = fmaf(r0, r0, s); s = fmaf(r1, r1, s);
        s = fmaf(r2, r2, s); s = fmaf(r3, r3, s);
        *(uint2*)(g_hi + gb + e) = H.u;
    }
    #pragma unroll
    for (int off = 16; off > 0; off >>= 1)
        s += __shfl_xor_sync(0xffffffffu, s, off);
    if (lane == 0) g_sq[row] = s;

    __syncthreads();
    atomicAdd(&g_colsum[t], s_col[t]);
    atomicAdd(&g_colsum[t + 256], s_col[t + 256]);
}

// ---------------- bandwidth + exp constant (256 threads) -------------------
__global__ void k_prep() {
    __shared__ double sh1[8], sh2[8];
    int t = threadIdx.x;
    int warp = t >> 5, lane = t & 31;
    double a = 0.0, b = 0.0;
    const float4* sq4 = (const float4*)g_sq;
    #pragma unroll
    for (int i = 0; i < 8; i++) {
        float4 f = sq4[t + 256 * i];
        a += (double)f.x + (double)f.y + (double)f.z + (double)f.w;
    }
    #pragma unroll
    for (int i = 0; i < 2; i++) {
        double v = (double)g_colsum[t + 256 * i];
        b += v * v;
    }
    #pragma unroll
    for (int off = 16; off > 0; off >>= 1) {
        a += __shfl_xor_sync(0xffffffffu, a, off);
        b += __shfl_xor_sync(0xffffffffu, b, off);
    }
    if (lane == 0) { sh1[warp] = a; sh2[warp] = b; }
    __syncthreads();
    if (t == 0) {
        double A = 0.0, B = 0.0;
        #pragma unroll
        for (int w = 0; w < 8; w++) { A += sh1[w]; B += sh2[w]; }
        double n = (double)NTOT;
        double sum_l2 = 2.0 * n * A - 2.0 * B;
        double bw = sum_l2 / (n * n - n);
        g_c = (float)(1.4426950408889634 / (4.0 * bw + 1e-8));
    }
}

// -------- persistent main: HMMA gram + fused RBF epilogue ------------------
__global__ void __launch_bounds__(256, 1) k_main() {
    __shared__ float s_sqi[128];
    __shared__ float s_sqj[256];
    extern __shared__ char dsm[];
    uint32_t sb = (smem_u32(dsm) + 1023) & ~1023u;   // 1KB-align ring

    int tid = threadIdx.x;
    int lid = tid & 31;
    int wid = tid >> 5;
    int wm = wid & 1, wn = wid >> 1;      // warp grid 2(m) x 4(n), 64x64 tiles
    int stride = gridDim.x;

    // tile decode: work unit -> (row0, col0, diag)
    auto decode = [](int bidx, int& r0, int& c0, int& dg) {
        int beta = bidx >> 1, h = bidx & 1;
        int Ip = (int)((sqrtf(8.0f * (float)beta + 1.0f) - 1.0f) * 0.5f);
        while ((Ip + 1) * (Ip + 2) / 2 <= beta) Ip++;
        while (Ip * (Ip + 1) / 2 > beta) Ip--;
        int Jp = beta - Ip * (Ip + 1) / 2;
        r0 = Jp * 256 + h * 128;          // 128 rows (CI = Jp <= CJ = Ip)
        c0 = Ip * 256;                    // 256 cols
        dg = (Jp == Ip);
    };

    // chunk loader: (row0, col0, chunk ck) -> ring slot
    auto load_chunk = [&](int r0, int c0, int ck, int slot) {
        uint32_t base = sb + slot * BUFB;
        int k0 = ck * KC;
        #pragma unroll
        for (int p = 0; p < 12; p++) {
            int qq = tid + 256 * p;           // 0..3071 16B-segments
            int isB = (qq >= 1024);
            int s = isB ? (qq - 1024) : qq;
            int r = s >> 3, c8 = s & 7;
            uint32_t sw = swz(r * 128 + c8 * 16);
            size_t eo = (size_t)((isB ? c0 : r0) + r) * DDIM + k0 + c8 * 8;
            cp_async16(base + (isB ? TILEA : 0) + sw, g_hi + eo);
        }
        CP_COMMIT();
    };

    int t = blockIdx.x;
    int row0, col0, dg;
    decode(t, row0, col0, dg);

    float cst = g_c;
    int fr = lid & 15;                       // row within 16-row group
    uint32_t fcol = ((lid >> 4) & 1) * 16;   // 16B k-half
    int g = lid >> 2, t4 = lid & 3;

    int q = 0;                               // global chunk counter
    load_chunk(row0, col0, 0, 0);
    load_chunk(row0, col0, 1, 1);

    while (true) {
        int tn = t + stride;
        bool hasNext = (tn < NTILES);
        int nrow0 = 0, ncol0 = 0, ndg = 0;
        if (hasNext) decode(tn, nrow0, ncol0, ndg);

        __syncthreads();                     // prior epilogue readers done
        if (tid < 128) s_sqi[tid] = g_sq[row0 + tid] * cst;
        s_sqj[tid] = g_sq[col0 + tid] * cst;

        float acc[4][8][4];
        #pragma unroll
        for (int mt = 0; mt < 4; mt++)
            #pragma unroll
            for (int nt = 0; nt < 8; nt++)
                #pragma unroll
                for (int k = 0; k < 4; k++) acc[mt][nt][k] = 0.f;

        for (int c = 0; c < NCH; c++, q++) {
            if (!hasNext && c == NCH - 1) CP_WAIT0(); else CP_WAIT1();
            __syncthreads();
            int slot2 = (q + 2) % 3;
            if (c < NCH - 2)      load_chunk(row0, col0, c + 2, slot2);
            else if (hasNext)     load_chunk(nrow0, ncol0, c - (NCH - 2), slot2);

            uint32_t base = sb + (q % 3) * BUFB;
            #pragma unroll
            for (int kk = 0; kk < 4; kk++) {
                uint32_t kb = kk * 32 + fcol;
                uint32_t ah[4][4];
                #pragma unroll
                for (int mt = 0; mt < 4; mt++) {
                    uint32_t sw = swz((wm * 64 + mt * 16 + fr) * 128 + kb);
                    ldsm_x4(ah[mt][0], ah[mt][1], ah[mt][2], ah[mt][3], base + sw);
                }
                #pragma unroll
                for (int p = 0; p < 4; p++) {
                    uint32_t sw = swz((wn * 64 + p * 16 + fr) * 128 + kb);
                    uint32_t bh0, bh1, bh2, bh3;
                    ldsm_x4(bh0, bh1, bh2, bh3, base + TILEA + sw);
                    #pragma unroll
                    for (int mt = 0; mt < 4; mt++) {
                        mma16816(acc[mt][2 * p],     ah[mt], bh0, bh2);
                        mma16816(acc[mt][2 * p + 1], ah[mt], bh1, bh3);
                    }
                }
            }
        }

        // ---- epilogue: t = min(2c*dot - (sqi+sqj)*c, 0); b=2^t;
        //      fs += b + b^2 + b^4 + b^8 + b^16  (next tile's loads in flight)
        float c2 = 2.0f * cst;
        double accd = 0.0;
        #pragma unroll
        for (int mt = 0; mt < 4; mt++) {
            float si0 = s_sqi[wm * 64 + mt * 16 + g];
            float si1 = s_sqi[wm * 64 + mt * 16 + g + 8];
            float fs = 0.f;
            #pragma unroll
            for (int nt = 0; nt < 8; nt++) {
                float sj0 = s_sqj[wn * 64 + nt * 8 + 2 * t4];
                float sj1 = s_sqj[wn * 64 + nt * 8 + 2 * t4 + 1];
                #pragma unroll
                for (int k = 0; k < 4; k++) {
                    float si = (k < 2) ? si0 : si1;
                    float sj = (k & 1) ? sj1 : sj0;
                    float tt = fminf(fmaf(c2, acc[mt][nt][k], -(si + sj)), 0.0f);
                    float b1 = ex2_approx(tt);
                    float p2 = b1 * b1;
                    float p4 = p2 * p2;
                    float p8 = p4 * p4;
                    float p16 = p8 * p8;
                    fs += (b1 + p2) + (p4 + p8) + p16;
                }
            }
            accd += (double)fs;
        }

        // warp-shuffle double reduction; one global atomic per warp
        #pragma unroll
        for (int off = 16; off > 0; off >>= 1)
            accd += __shfl_xor_sync(0xffffffffu, accd, off);
        if (lid == 0) {
            double v = accd * (dg ? 1.0 : 2.0);
            int rh = (row0 >= NS), ch = (col0 >= NS);
            int bin = (rh & ch) ? 1 : ((!rh && !ch) ? 0 : 2);
            atomicAdd(&g_bins[bin], v);
        }

        if (!hasNext) break;
        t = tn; row0 = nrow0; col0 = ncol0; dg = ndg;
    }
}

// ---- finalize + reset accumulator state for the next graph replay ---------
__global__ void k_final(float* out) {
    int t = threadIdx.x;
    if (t == 0) {
        double ns2 = (double)NS * (double)NS;
        out[0] = (float)((g_bins[0] + g_bins[1] - g_bins[2]) / ns2);
    }
    __syncthreads();
    if (t < 3) g_bins[t] = 0.0;
    g_colsum[t] = 0.f;
    g_colsum[t + 256] = 0.f;
}

extern "C" void kernel_launch(void* const* d_in, const int* in_sizes, int n_in,
                              void* d_out, int out_size) {
    const float* src = (const float*)d_in[0];
    const float* tgt = (const float*)d_in[1];
    float* out = (float*)d_out;

    int nsm = 0;
    cudaDeviceGetAttribute(&nsm, cudaDevAttrMultiProcessorCount, 0);
    if (nsm <= 0) nsm = 148;
    int grid = (nsm < NTILES) ? nsm : NTILES;

    cudaFuncSetAttribute(k_main, cudaFuncAttributeMaxDynamicSharedMemorySize,
                         SMEM_DYN);
    k_convert<<<NTOT / 8, 256>>>(src, tgt);
    k_prep<<<1, 256>>>();
    k_main<<<grid, 256, SMEM_DYN>>>();
    k_final<<<1, 256>>>(out);
}

// round 13
// speedup vs baseline: 6.2276x; 1.0457x over previous
#include <cuda_runtime.h>
#include <cuda_bf16.h>
#include <math.h>
#include <stdint.h>

// ---------------------------------------------------------------------------
// MMDLoss: source (4096,512) f32, target (4096,512) f32 -> scalar f32
//
// SINGLE persistent megakernel (1 CTA/SM):
//   phase 1: f32 -> bf16 convert + row sq-norms (of bf16) + column sums
//   grid barrier (flag-based; all CTAs resident)
//   phase 2: every CTA redundantly computes the bandwidth constant
//   phase 3: HMMA gram, CTA tile 128x256 (warp tile 64x64), 3-slot cp.async
//            ring with cross-tile prefetch; fused RBF epilogue
//   phase 4: done-counter; last CTA finalizes output + resets state
// Bandwidth closed-form: sum(l2) = 2N*sum(sq) - 2*||colsum||^2.
// 5-bandwidth RBF collapses to b + b^2 + b^4 + b^8 + b^16, b = exp(-l2/(4bw)).
// ---------------------------------------------------------------------------

#define NS    4096
#define NTOT  8192
#define DDIM  512
#define NCOARSE 528           // 32*33/2 coarse 256x256 triangular pairs
#define NTILES (2 * NCOARSE)  // 1056 work units (128x256 each)
#define KC    64              // K elements per chunk (128B row)
#define NCH   8               // 512/64

#define TILEA 16384           // A: 128 rows * 128B
#define TILEB_SZ 32768        // B: 256 rows * 128B
#define BUFB  (TILEA + TILEB_SZ)          // 48KB per ring slot
#define SMEM_DYN (1024 + 3 * BUFB)        // ~148.5 KB -> 1 CTA/SM

__device__ __nv_bfloat16 g_hi[NTOT * DDIM];   // 8 MB
__device__ float  g_sq[NTOT];       // sq of bf16-rounded rows
__device__ float  g_colsum[DDIM];   // zero-init; finalizer re-zeroes
__device__ double g_bins[3];        // Sxx, Syy, Scross; finalizer re-zeroes
__device__ unsigned g_bar_count = 0;
__device__ volatile unsigned g_bar_gen = 0;   // monotone across replays
__device__ unsigned g_done = 0;

// ------------------------------ PTX helpers -------------------------------
__device__ __forceinline__ uint32_t smem_u32(const void* p) {
    uint32_t a;
    asm("{ .reg .u64 t; cvta.to.shared.u64 t, %1; cvt.u32.u64 %0, t; }"
        : "=r"(a) : "l"(p));
    return a;
}
__device__ __forceinline__ void cp_async16(uint32_t sa, const void* g) {
    asm volatile("cp.async.cg.shared.global [%0], [%1], 16;"
                 :: "r"(sa), "l"(g) : "memory");
}
#define CP_COMMIT() asm volatile("cp.async.commit_group;" ::: "memory")
#define CP_WAIT1()  asm volatile("cp.async.wait_group 1;" ::: "memory")
#define CP_WAIT0()  asm volatile("cp.async.wait_group 0;" ::: "memory")

__device__ __forceinline__ void ldsm_x4(uint32_t& r0, uint32_t& r1,
                                        uint32_t& r2, uint32_t& r3, uint32_t a) {
    asm volatile("ldmatrix.sync.aligned.m8n8.x4.shared.b16 {%0,%1,%2,%3}, [%4];"
                 : "=r"(r0), "=r"(r1), "=r"(r2), "=r"(r3) : "r"(a));
}
__device__ __forceinline__ void mma16816(float* c, const uint32_t* a,
                                         uint32_t b0, uint32_t b1) {
    asm volatile(
        "mma.sync.aligned.m16n8k16.row.col.f32.bf16.bf16.f32 "
        "{%0,%1,%2,%3}, {%4,%5,%6,%7}, {%8,%9}, {%0,%1,%2,%3};"
        : "+f"(c[0]), "+f"(c[1]), "+f"(c[2]), "+f"(c[3])
        : "r"(a[0]), "r"(a[1]), "r"(a[2]), "r"(a[3]), "r"(b0), "r"(b1));
}
__device__ __forceinline__ float ex2_approx(float x) {
    float r;
    asm("ex2.approx.ftz.f32 %0, %1;" : "=f"(r) : "f"(x));
    return r;
}
// SW128 swizzle for 128-byte rows (atom: 8 rows x 128B)
__device__ __forceinline__ uint32_t swz(uint32_t bo) {
    return bo ^ ((bo >> 3) & 0x70);
}

// flag-based grid barrier; safe: all CTAs co-resident (1 CTA/SM by smem)
__device__ __forceinline__ void grid_barrier() {
    __syncthreads();
    if (threadIdx.x == 0) {
        __threadfence();
        unsigned gen = g_bar_gen;
        if (atomicAdd(&g_bar_count, 1) == gridDim.x - 1) {
            g_bar_count = 0;
            __threadfence();
            g_bar_gen = gen + 1;
        } else {
            while (g_bar_gen == gen) { }
        }
        __threadfence();
    }
    __syncthreads();
}

// -------------------- the megakernel ---------------------------------------
__global__ void __launch_bounds__(256, 1) k_all(const float* __restrict__ src,
                                                const float* __restrict__ tgt,
                                                float* __restrict__ out) {
    __shared__ float s_col[DDIM];
    __shared__ float s_sqi[128];
    __shared__ float s_sqj[256];
    __shared__ double sh1[8], sh2[8];
    __shared__ float s_cst;
    extern __shared__ char dsm[];
    uint32_t sb = (smem_u32(dsm) + 1023) & ~1023u;   // 1KB-align ring

    int tid = threadIdx.x;
    int lid = tid & 31;
    int wid = tid >> 5;

    // ================= phase 1: convert + sq + colsum ======================
    s_col[tid] = 0.f; s_col[tid + 256] = 0.f;
    __syncthreads();

    for (int rb = blockIdx.x; rb < NTOT / 8; rb += gridDim.x) {
        int row = rb * 8 + wid;               // one row per warp
        const float* p = (row < NS) ? (src + (size_t)row * DDIM)
                                    : (tgt + (size_t)(row - NS) * DDIM);
        size_t gb = (size_t)row * DDIM;
        float s = 0.f;
        #pragma unroll
        for (int v = 0; v < 4; v++) {
            int e = (lid + v * 32) * 4;
            float4 f = *(const float4*)(p + e);
            atomicAdd(&s_col[e + 0], f.x);
            atomicAdd(&s_col[e + 1], f.y);
            atomicAdd(&s_col[e + 2], f.z);
            atomicAdd(&s_col[e + 3], f.w);
            union { __nv_bfloat16 h[4]; uint2 u; } H;
            H.h[0] = __float2bfloat16(f.x);
            H.h[1] = __float2bfloat16(f.y);
            H.h[2] = __float2bfloat16(f.z);
            H.h[3] = __float2bfloat16(f.w);
            float r0 = __bfloat162float(H.h[0]);
            float r1 = __bfloat162float(H.h[1]);
            float r2 = __bfloat162float(H.h[2]);
            float r3 = __bfloat162float(H.h[3]);
            s = fmaf(r0, r0, s); s = fmaf(r1, r1, s);
            s = fmaf(r2, r2, s); s = fmaf(r3, r3, s);
            *(uint2*)(g_hi + gb + e) = H.u;
        }
        #pragma unroll
        for (int off = 16; off > 0; off >>= 1)
            s += __shfl_xor_sync(0xffffffffu, s, off);
        if (lid == 0) g_sq[row] = s;
    }
    __syncthreads();
    atomicAdd(&g_colsum[tid], s_col[tid]);
    atomicAdd(&g_colsum[tid + 256], s_col[tid + 256]);
    __threadfence();

    grid_barrier();

    // ================= phase 2: bandwidth constant (redundant/CTA) =========
    {
        double a = 0.0, b = 0.0;
        const float4* sq4 = (const float4*)g_sq;
        #pragma unroll
        for (int i = 0; i < 8; i++) {
            float4 f = sq4[tid + 256 * i];
            a += (double)f.x + (double)f.y + (double)f.z + (double)f.w;
        }
        #pragma unroll
        for (int i = 0; i < 2; i++) {
            double v = (double)g_colsum[tid + 256 * i];
            b += v * v;
        }
        #pragma unroll
        for (int off = 16; off > 0; off >>= 1) {
            a += __shfl_xor_sync(0xffffffffu, a, off);
            b += __shfl_xor_sync(0xffffffffu, b, off);
        }
        if (lid == 0) { sh1[wid] = a; sh2[wid] = b; }
        __syncthreads();
        if (tid == 0) {
            double A = 0.0, B = 0.0;
            #pragma unroll
            for (int w = 0; w < 8; w++) { A += sh1[w]; B += sh2[w]; }
            double n = (double)NTOT;
            double sum_l2 = 2.0 * n * A - 2.0 * B;
            double bw = sum_l2 / (n * n - n);
            s_cst = (float)(1.4426950408889634 / (4.0 * bw + 1e-8));
        }
        __syncthreads();
    }
    float cst = s_cst;

    // ================= phase 3: persistent gram + RBF epilogue =============
    int wm = wid & 1, wn = wid >> 1;      // warp grid 2(m) x 4(n), 64x64 tiles
    int stride = gridDim.x;

    auto decode = [](int bidx, int& r0, int& c0, int& dg) {
        int beta = bidx >> 1, h = bidx & 1;
        int Ip = (int)((sqrtf(8.0f * (float)beta + 1.0f) - 1.0f) * 0.5f);
        while ((Ip + 1) * (Ip + 2) / 2 <= beta) Ip++;
        while (Ip * (Ip + 1) / 2 > beta) Ip--;
        int Jp = beta - Ip * (Ip + 1) / 2;
        r0 = Jp * 256 + h * 128;
        c0 = Ip * 256;
        dg = (Jp == Ip);
    };

    auto load_chunk = [&](int r0, int c0, int ck, int slot) {
        uint32_t base = sb + slot * BUFB;
        int k0 = ck * KC;
        #pragma unroll
        for (int p = 0; p < 12; p++) {
            int qq = tid + 256 * p;           // 0..3071 16B-segments
            int isB = (qq >= 1024);
            int s = isB ? (qq - 1024) : qq;
            int r = s >> 3, c8 = s & 7;
            uint32_t sw = swz(r * 128 + c8 * 16);
            size_t eo = (size_t)((isB ? c0 : r0) + r) * DDIM + k0 + c8 * 8;
            cp_async16(base + (isB ? TILEA : 0) + sw, g_hi + eo);
        }
        CP_COMMIT();
    };

    int t = blockIdx.x;
    if (t < NTILES) {
        int row0, col0, dg;
        decode(t, row0, col0, dg);

        int fr = lid & 15;
        uint32_t fcol = ((lid >> 4) & 1) * 16;
        int g = lid >> 2, t4 = lid & 3;

        int q = 0;                            // global chunk counter
        load_chunk(row0, col0, 0, 0);
        load_chunk(row0, col0, 1, 1);

        while (true) {
            int tn = t + stride;
            bool hasNext = (tn < NTILES);
            int nrow0 = 0, ncol0 = 0, ndg = 0;
            if (hasNext) decode(tn, nrow0, ncol0, ndg);

            __syncthreads();                  // prior epilogue readers done
            if (tid < 128) s_sqi[tid] = g_sq[row0 + tid] * cst;
            s_sqj[tid] = g_sq[col0 + tid] * cst;

            float acc[4][8][4];
            #pragma unroll
            for (int mt = 0; mt < 4; mt++)
                #pragma unroll
                for (int nt = 0; nt < 8; nt++)
                    #pragma unroll
                    for (int k = 0; k < 4; k++) acc[mt][nt][k] = 0.f;

            for (int c = 0; c < NCH; c++, q++) {
                if (!hasNext && c == NCH - 1) CP_WAIT0(); else CP_WAIT1();
                __syncthreads();
                int slot2 = (q + 2) % 3;
                if (c < NCH - 2)      load_chunk(row0, col0, c + 2, slot2);
                else if (hasNext)     load_chunk(nrow0, ncol0, c - (NCH - 2), slot2);

                uint32_t base = sb + (q % 3) * BUFB;
                #pragma unroll
                for (int kk = 0; kk < 4; kk++) {
                    uint32_t kb = kk * 32 + fcol;
                    uint32_t ah[4][4];
                    #pragma unroll
                    for (int mt = 0; mt < 4; mt++) {
                        uint32_t sw = swz((wm * 64 + mt * 16 + fr) * 128 + kb);
                        ldsm_x4(ah[mt][0], ah[mt][1], ah[mt][2], ah[mt][3], base + sw);
                    }
                    #pragma unroll
                    for (int p = 0; p < 4; p++) {
                        uint32_t sw = swz((wn * 64 + p * 16 + fr) * 128 + kb);
                        uint32_t bh0, bh1, bh2, bh3;
                        ldsm_x4(bh0, bh1, bh2, bh3, base + TILEA + sw);
                        #pragma unroll
                        for (int mt = 0; mt < 4; mt++) {
                            mma16816(acc[mt][2 * p],     ah[mt], bh0, bh2);
                            mma16816(acc[mt][2 * p + 1], ah[mt], bh1, bh3);
                        }
                    }
                }
            }

            // epilogue: tt = min(2c*dot - (sqi+sqj)*c, 0); b=2^tt
            float c2 = 2.0f * cst;
            double accd = 0.0;
            #pragma unroll
            for (int mt = 0; mt < 4; mt++) {
                float si0 = s_sqi[wm * 64 + mt * 16 + g];
                float si1 = s_sqi[wm * 64 + mt * 16 + g + 8];
                float fs = 0.f;
                #pragma unroll
                for (int nt = 0; nt < 8; nt++) {
                    float sj0 = s_sqj[wn * 64 + nt * 8 + 2 * t4];
                    float sj1 = s_sqj[wn * 64 + nt * 8 + 2 * t4 + 1];
                    #pragma unroll
                    for (int k = 0; k < 4; k++) {
                        float si = (k < 2) ? si0 : si1;
                        float sj = (k & 1) ? sj1 : sj0;
                        float tt = fminf(fmaf(c2, acc[mt][nt][k], -(si + sj)), 0.0f);
                        float b1 = ex2_approx(tt);
                        float p2 = b1 * b1;
                        float p4 = p2 * p2;
                        float p8 = p4 * p4;
                        float p16 = p8 * p8;
                        fs += (b1 + p2) + (p4 + p8) + p16;
                    }
                }
                accd += (double)fs;
            }

            #pragma unroll
            for (int off = 16; off > 0; off >>= 1)
                accd += __shfl_xor_sync(0xffffffffu, accd, off);
            if (lid == 0) {
                double v = accd * (dg ? 1.0 : 2.0);
                int rh = (row0 >= NS), ch = (col0 >= NS);
                int bin = (rh & ch) ? 1 : ((!rh && !ch) ? 0 : 2);
                atomicAdd(&g_bins[bin], v);
            }

            if (!hasNext) break;
            t = tn; row0 = nrow0; col0 = ncol0; dg = ndg;
        }
    }

    // ================= phase 4: finalize (last CTA) ========================
    __threadfence();
    __syncthreads();
    if (tid == 0) {
        if (atomicAdd(&g_done, 1) == gridDim.x - 1) {
            __threadfence();
            double ns2 = (double)NS * (double)NS;
            out[0] = (float)((g_bins[0] + g_bins[1] - g_bins[2]) / ns2);
            g_bins[0] = 0.0; g_bins[1] = 0.0; g_bins[2] = 0.0;
            for (int i = 0; i < DDIM; i++) g_colsum[i] = 0.f;
            __threadfence();
            g_done = 0;
        }
    }
}

extern "C" void kernel_launch(void* const* d_in, const int* in_sizes, int n_in,
                              void* d_out, int out_size) {
    const float* src = (const float*)d_in[0];
    const float* tgt = (const float*)d_in[1];
    float* out = (float*)d_out;

    int nsm = 0;
    cudaDeviceGetAttribute(&nsm, cudaDevAttrMultiProcessorCount, 0);
    if (nsm <= 0) nsm = 148;
    int grid = (nsm < NTILES) ? nsm : NTILES;

    cudaFuncSetAttribute(k_all, cudaFuncAttributeMaxDynamicSharedMemorySize,
                         SMEM_DYN);
    k_all<<<grid, 256, SMEM_DYN>>>(src, tgt, out);
}